// round 3
// baseline (speedup 1.0000x reference)
#include <cuda_runtime.h>
#include <cstdint>

// ---------------- problem constants (fixed by the reference) ----------------
#define BS      8
#define NQ      900
#define EMBED   256
#define HEADS   8
#define HEAD_DIM 32
#define LEVELS  4
#define POINTS  4
#define NV      13294          // 100*100 + 50*50 + 25*25 + 13*13
#define NBQ     (BS * NQ)      // 7200

__device__ __constant__ int c_LH[4] = {100, 50, 25, 13};
__device__ __constant__ int c_LW[4] = {100, 50, 25, 13};
__device__ __constant__ int c_LS[4] = {0, 10000, 12500, 13125};

// ---------------- scratch (static device allocations, allowed) --------------
__device__ float g_v[(size_t)BS * NV * EMBED];     // projected value, ~109 MB
__device__ float g_off[(size_t)NBQ * 256];         // sampling offsets raw
__device__ float g_aw[(size_t)NBQ * 128];          // attention logits
__device__ float g_attn[(size_t)NBQ * EMBED];      // attention output pre-Wout

// ---------------- f32x2 helpers ---------------------------------------------
__device__ __forceinline__ unsigned long long pack2(float x, float y) {
    unsigned long long r;
    asm("mov.b64 %0, {%1, %2};" : "=l"(r) : "f"(x), "f"(y));
    return r;
}
__device__ __forceinline__ void fma2(unsigned long long& d,
                                     unsigned long long a,
                                     unsigned long long b) {
    asm("fma.rn.f32x2 %0, %1, %2, %0;" : "+l"(d) : "l"(a), "l"(b));
}

// ---------------- fp32 tiled GEMM (128x128x16, 8x8/thread, f32x2 FMA) -------
// C = A(MxK) * B(KxN) + bias (+ resid).  N must be a multiple of 128.
#define BM 128
#define BN 128
#define BK 16

__global__ __launch_bounds__(256, 2)
void gemm_bias_kernel(const float* __restrict__ A, const float* __restrict__ B,
                      const float* __restrict__ bias, const float* __restrict__ resid,
                      float* __restrict__ C, int M, int N, int K, int addResid)
{
    __shared__ float As[2][BK][BM + 4];   // transposed A tile: As[k][m]
    __shared__ float Bs[2][BK][BN];       // Bs[k][n]

    const int tid = threadIdx.x;          // 256 threads
    const int m0 = blockIdx.y * BM;
    const int n0 = blockIdx.x * BN;

    // output micro-tile 8x8
    const int tr = (tid >> 4) * 8;        // 0..120
    const int tc = (tid & 15) * 8;        // 0..120

    // A load: 512 float4/tile, 2 per thread. idx -> row=idx>>2, kq=(idx&3)*4
    const int a_row0 = tid >> 2;          // idx = tid
    const int a_kq   = (tid & 3) * 4;
    const int a_row1 = a_row0 + 64;       // idx = tid + 256

    // B load: 512 float4/tile, 2 per thread. idx -> krow=idx>>5, col=(idx&31)*4
    const int b_k0  = tid >> 5;           // 0..7
    const int b_col = (tid & 31) * 4;
    const int b_k1  = b_k0 + 8;

    unsigned long long acc[8][4];
#pragma unroll
    for (int i = 0; i < 8; i++)
#pragma unroll
        for (int j = 0; j < 4; j++) acc[i][j] = 0ull;

    const int ntiles = K / BK;

    // --- prologue: load tile 0 straight into smem buf 0 ---
    {
        float4 av0 = make_float4(0.f, 0.f, 0.f, 0.f), av1 = av0;
        if (m0 + a_row0 < M) av0 = *reinterpret_cast<const float4*>(&A[(size_t)(m0 + a_row0) * K + a_kq]);
        if (m0 + a_row1 < M) av1 = *reinterpret_cast<const float4*>(&A[(size_t)(m0 + a_row1) * K + a_kq]);
        As[0][a_kq + 0][a_row0] = av0.x; As[0][a_kq + 1][a_row0] = av0.y;
        As[0][a_kq + 2][a_row0] = av0.z; As[0][a_kq + 3][a_row0] = av0.w;
        As[0][a_kq + 0][a_row1] = av1.x; As[0][a_kq + 1][a_row1] = av1.y;
        As[0][a_kq + 2][a_row1] = av1.z; As[0][a_kq + 3][a_row1] = av1.w;
        *reinterpret_cast<float4*>(&Bs[0][b_k0][b_col]) =
            *reinterpret_cast<const float4*>(&B[(size_t)b_k0 * N + n0 + b_col]);
        *reinterpret_cast<float4*>(&Bs[0][b_k1][b_col]) =
            *reinterpret_cast<const float4*>(&B[(size_t)b_k1 * N + n0 + b_col]);
    }
    __syncthreads();

    int buf = 0;
    for (int kt = 0; kt < ntiles; kt++) {
        // stage next tile into registers
        float4 av0, av1, bv0, bv1;
        const bool more = (kt + 1 < ntiles);
        if (more) {
            const int kb = (kt + 1) * BK;
            av0 = make_float4(0.f, 0.f, 0.f, 0.f); av1 = av0;
            if (m0 + a_row0 < M) av0 = *reinterpret_cast<const float4*>(&A[(size_t)(m0 + a_row0) * K + kb + a_kq]);
            if (m0 + a_row1 < M) av1 = *reinterpret_cast<const float4*>(&A[(size_t)(m0 + a_row1) * K + kb + a_kq]);
            bv0 = *reinterpret_cast<const float4*>(&B[(size_t)(kb + b_k0) * N + n0 + b_col]);
            bv1 = *reinterpret_cast<const float4*>(&B[(size_t)(kb + b_k1) * N + n0 + b_col]);
        }

        // compute on current buffer
#pragma unroll
        for (int k = 0; k < BK; k++) {
            float4 a0 = *reinterpret_cast<const float4*>(&As[buf][k][tr]);
            float4 a1 = *reinterpret_cast<const float4*>(&As[buf][k][tr + 4]);
            ulonglong2 bA = *reinterpret_cast<const ulonglong2*>(&Bs[buf][k][tc]);
            ulonglong2 bB = *reinterpret_cast<const ulonglong2*>(&Bs[buf][k][tc + 4]);
            unsigned long long bb[4] = {bA.x, bA.y, bB.x, bB.y};
            float a[8] = {a0.x, a0.y, a0.z, a0.w, a1.x, a1.y, a1.z, a1.w};
#pragma unroll
            for (int i = 0; i < 8; i++) {
                unsigned long long ai = pack2(a[i], a[i]);
#pragma unroll
                for (int j = 0; j < 4; j++) fma2(acc[i][j], ai, bb[j]);
            }
        }

        if (more) {
            const int nb = buf ^ 1;
            As[nb][a_kq + 0][a_row0] = av0.x; As[nb][a_kq + 1][a_row0] = av0.y;
            As[nb][a_kq + 2][a_row0] = av0.z; As[nb][a_kq + 3][a_row0] = av0.w;
            As[nb][a_kq + 0][a_row1] = av1.x; As[nb][a_kq + 1][a_row1] = av1.y;
            As[nb][a_kq + 2][a_row1] = av1.z; As[nb][a_kq + 3][a_row1] = av1.w;
            *reinterpret_cast<float4*>(&Bs[nb][b_k0][b_col]) = bv0;
            *reinterpret_cast<float4*>(&Bs[nb][b_k1][b_col]) = bv1;
            __syncthreads();
            buf = nb;
        }
    }

    // --- epilogue ---
    float4 bias0 = *reinterpret_cast<const float4*>(&bias[n0 + tc]);
    float4 bias1 = *reinterpret_cast<const float4*>(&bias[n0 + tc + 4]);
    const float bb[8] = {bias0.x, bias0.y, bias0.z, bias0.w,
                         bias1.x, bias1.y, bias1.z, bias1.w};
#pragma unroll
    for (int i = 0; i < 8; i++) {
        const int m = m0 + tr + i;
        if (m >= M) continue;
        float v[8];
#pragma unroll
        for (int j = 0; j < 4; j++) {
            float2 f = *reinterpret_cast<float2*>(&acc[i][j]);
            v[2 * j + 0] = f.x + bb[2 * j + 0];
            v[2 * j + 1] = f.y + bb[2 * j + 1];
        }
        if (addResid) {
            float4 r0 = *reinterpret_cast<const float4*>(&resid[(size_t)m * N + n0 + tc]);
            float4 r1 = *reinterpret_cast<const float4*>(&resid[(size_t)m * N + n0 + tc + 4]);
            v[0] += r0.x; v[1] += r0.y; v[2] += r0.z; v[3] += r0.w;
            v[4] += r1.x; v[5] += r1.y; v[6] += r1.z; v[7] += r1.w;
        }
        *reinterpret_cast<float4*>(&C[(size_t)m * N + n0 + tc]) =
            make_float4(v[0], v[1], v[2], v[3]);
        *reinterpret_cast<float4*>(&C[(size_t)m * N + n0 + tc + 4]) =
            make_float4(v[4], v[5], v[6], v[7]);
    }
}

// ---------------- sampling kernel: softmax + bilinear gather ----------------
__global__ __launch_bounds__(256)
void msda_sample_kernel(const float* __restrict__ rp)
{
    const int bq = blockIdx.x;          // 0..NBQ-1
    const int b = bq / NQ;
    const int tid = threadIdx.x;

    __shared__ float s_aw[128];
    __shared__ int   s_pos[128][4];
    __shared__ float s_wt[128][4];

    if (tid < 128) s_aw[tid] = g_aw[(size_t)bq * 128 + tid];
    __syncthreads();

    // per-head softmax over 16 (levels*points)
    if (tid < HEADS) {
        const int base = tid * 16;
        float mx = -1e30f;
#pragma unroll
        for (int i = 0; i < 16; i++) mx = fmaxf(mx, s_aw[base + i]);
        float e[16];
        float sum = 0.f;
#pragma unroll
        for (int i = 0; i < 16; i++) { e[i] = __expf(s_aw[base + i] - mx); sum += e[i]; }
        float inv = 1.f / sum;
#pragma unroll
        for (int i = 0; i < 16; i++) s_aw[base + i] = e[i] * inv;
    }
    __syncthreads();

    // per-sample corner weights/indices (128 samples = heads*levels*points)
    if (tid < 128) {
        const int s = tid;
        const int l = (s >> 2) & 3;
        const float aw = s_aw[s];
        const float offx = g_off[(size_t)bq * 256 + s * 2];
        const float offy = g_off[(size_t)bq * 256 + s * 2 + 1];
        const float rx = rp[((size_t)bq * LEVELS + l) * 2];
        const float ry = rp[((size_t)bq * LEVELS + l) * 2 + 1];
        const int W = c_LW[l], H = c_LH[l], st = c_LS[l];

        const float locx = rx + offx / (float)W;
        const float locy = ry + offy / (float)H;
        const float x = locx * (float)W - 0.5f;
        const float y = locy * (float)H - 0.5f;
        const float x0f = floorf(x), y0f = floorf(y);
        const float lx = x - x0f, ly = y - y0f;
        const int x0 = (int)x0f, y0 = (int)y0f;

#pragma unroll
        for (int c = 0; c < 4; c++) {
            const int dx = c & 1, dy = c >> 1;
            const int xi = x0 + dx, yi = y0 + dy;
            const float wx = dx ? lx : (1.f - lx);
            const float wy = dy ? ly : (1.f - ly);
            const bool valid = (xi >= 0) && (xi < W) && (yi >= 0) && (yi < H);
            const int xc = min(max(xi, 0), W - 1);
            const int yc = min(max(yi, 0), H - 1);
            s_pos[s][c] = st + yc * W + xc;
            s_wt[s][c] = valid ? (wx * wy * aw) : 0.f;
        }
    }
    __syncthreads();

    // accumulate: thread (h, d) — each warp covers one head, coalesced 128B loads
    const int h = tid >> 5;
    const float* vb = g_v + (size_t)b * NV * EMBED + tid;   // tid = h*32+d column
    float acc = 0.f;
#pragma unroll
    for (int i = 0; i < 16; i++) {
        const int s = h * 16 + i;
#pragma unroll
        for (int c = 0; c < 4; c++) {
            acc = fmaf(s_wt[s][c], __ldg(vb + (size_t)s_pos[s][c] * EMBED), acc);
        }
    }
    g_attn[(size_t)bq * EMBED + tid] = acc;
}

// ---------------- launch --------------------------------------------------
extern "C" void kernel_launch(void* const* d_in, const int* in_sizes, int n_in,
                              void* d_out, int out_size)
{
    const float* query  = (const float*)d_in[0];
    const float* value  = (const float*)d_in[1];
    const float* rp     = (const float*)d_in[2];
    // d_in[3] = spatial_shapes (int32) — compile-time constants here
    const float* W_off  = (const float*)d_in[4];
    const float* b_off  = (const float*)d_in[5];
    const float* W_attn = (const float*)d_in[6];
    const float* b_attn = (const float*)d_in[7];
    const float* W_v    = (const float*)d_in[8];
    const float* b_v    = (const float*)d_in[9];
    const float* W_out  = (const float*)d_in[10];
    const float* b_out  = (const float*)d_in[11];
    float* out = (float*)d_out;

    float *pv, *poff, *paw, *pattn;
    cudaGetSymbolAddress((void**)&pv,    g_v);
    cudaGetSymbolAddress((void**)&poff,  g_off);
    cudaGetSymbolAddress((void**)&paw,   g_aw);
    cudaGetSymbolAddress((void**)&pattn, g_attn);

    // 1) value projection: (BS*NV, 256) @ (256, 256) + b_v
    {
        const int M = BS * NV;
        dim3 grid(EMBED / BN, (M + BM - 1) / BM);
        gemm_bias_kernel<<<grid, 256>>>(value, W_v, b_v, nullptr, pv, M, EMBED, EMBED, 0);
    }
    // 2) offsets: (NBQ, 256) @ (256, 256) + b_off
    {
        dim3 grid(256 / BN, (NBQ + BM - 1) / BM);
        gemm_bias_kernel<<<grid, 256>>>(query, W_off, b_off, nullptr, poff, NBQ, 256, EMBED, 0);
    }
    // 3) attention logits: (NBQ, 256) @ (256, 128) + b_attn
    {
        dim3 grid(128 / BN, (NBQ + BM - 1) / BM);
        gemm_bias_kernel<<<grid, 256>>>(query, W_attn, b_attn, nullptr, paw, NBQ, 128, EMBED, 0);
    }
    // 4) softmax + bilinear sampling
    msda_sample_kernel<<<NBQ, 256>>>(rp);

    // 5) output projection + residual: (NBQ,256) @ (256,256) + b_out + query
    {
        dim3 grid(EMBED / BN, (NBQ + BM - 1) / BM);
        gemm_bias_kernel<<<grid, 256>>>(pattn, W_out, b_out, query, out, NBQ, EMBED, EMBED, 1);
    }
}

// round 5
// speedup vs baseline: 1.9844x; 1.9844x over previous
#include <cuda_runtime.h>
#include <cuda_bf16.h>
#include <cstdint>

// ---------------- problem constants ----------------
#define BS      8
#define NQ      900
#define EMBED   256
#define HEADS   8
#define LEVELS  4
#define POINTS  4
#define NV      13294
#define NBQ     (BS * NQ)      // 7200
#define KDIM    256

__device__ __constant__ int c_LH[4] = {100, 50, 25, 13};
__device__ __constant__ int c_LW[4] = {100, 50, 25, 13};
__device__ __constant__ int c_LS[4] = {0, 10000, 12500, 13125};

// ---------------- scratch ----------------
__device__ float g_v[(size_t)BS * NV * EMBED];
__device__ float g_off[(size_t)NBQ * 256];
__device__ float g_aw[(size_t)NBQ * 128];
__device__ float g_attn[(size_t)NBQ * EMBED];

// pre-converted weights as MMA "B" operand: [N, K] row-major, bf16 hi/lo
__device__ __nv_bfloat16 g_Bvh[256 * 256], g_Bvl[256 * 256];
__device__ __nv_bfloat16 g_Boh[256 * 256], g_Bol[256 * 256];
__device__ __nv_bfloat16 g_Bah[128 * 256], g_Bal[128 * 256];
__device__ __nv_bfloat16 g_Buh[256 * 256], g_Bul[256 * 256];

// ---------------- helpers ----------------
__device__ __forceinline__ uint32_t pack_bf16(float x, float y) {
    __nv_bfloat162 h = __floats2bfloat162_rn(x, y);
    return *reinterpret_cast<uint32_t*>(&h);
}

__device__ __forceinline__ void mma_bf16(float d[4],
                                         uint32_t a0, uint32_t a1, uint32_t a2, uint32_t a3,
                                         uint32_t b0, uint32_t b1) {
    asm volatile(
        "mma.sync.aligned.m16n8k16.row.col.f32.bf16.bf16.f32 "
        "{%0,%1,%2,%3}, {%4,%5,%6,%7}, {%8,%9}, {%0,%1,%2,%3};"
        : "+f"(d[0]), "+f"(d[1]), "+f"(d[2]), "+f"(d[3])
        : "r"(a0), "r"(a1), "r"(a2), "r"(a3), "r"(b0), "r"(b1));
}

// ---------------- weight conversion: W[K,N] fp32 -> B[N,K] bf16 hi/lo -------
__global__ void conv_w_kernel(const float* __restrict__ W,
                              __nv_bfloat16* __restrict__ Bh,
                              __nv_bfloat16* __restrict__ Bl, int N)
{
    int i = blockIdx.x * 256 + threadIdx.x;
    if (i >= KDIM * N) return;
    int k = i / N, n = i % N;
    float x = W[i];
    __nv_bfloat16 hb = __float2bfloat16(x);
    float lo = x - __bfloat162float(hb);
    Bh[(size_t)n * KDIM + k] = hb;
    Bl[(size_t)n * KDIM + k] = __float2bfloat16(lo);
}

// ---------------- HMMA GEMM: C[M,Ntot] = A[M,256] @ B[N,256]^T + bias (+resid)
// CTA 128x128, KC=32 double-buffered, bf16x3 split, mma.sync m16n8k16.
#define KC 32
#define WPR 20                         // words per smem row (32 bf16 + 8 pad)
#define A_HI 0
#define A_LO (128 * WPR)               // 2560
#define B_HI (2 * 128 * WPR)           // 5120
#define B_LO (3 * 128 * WPR)           // 7680
#define STAGE_WORDS (4 * 128 * WPR)    // 10240
#define DSMEM_BYTES (2 * STAGE_WORDS * 4)  // 81920

__global__ __launch_bounds__(256, 1)
void mma_gemm_kernel(const float* __restrict__ A,
                     const __nv_bfloat16* __restrict__ Bh,
                     const __nv_bfloat16* __restrict__ Bl,
                     const float* __restrict__ bias,
                     const float* __restrict__ resid,
                     float* __restrict__ C,
                     int M, int Ntot)
{
    extern __shared__ uint32_t smw[];
    __shared__ float s_bias[128];

    const int tid = threadIdx.x;
    const int wid = tid >> 5;
    const int lane = tid & 31;
    const int g = lane >> 2;            // group row 0..7
    const int tig = lane & 3;           // thread in group
    const int wm = wid & 3;             // warp m index (4)
    const int wn = wid >> 2;            // warp n index (2)
    const int m0 = blockIdx.y * 128;
    const int n0 = blockIdx.x * 128;

    if (tid < 128) s_bias[tid] = bias[n0 + tid];

    float acc[2][8][4];
#pragma unroll
    for (int mt = 0; mt < 2; mt++)
#pragma unroll
        for (int nt = 0; nt < 8; nt++)
#pragma unroll
            for (int q = 0; q < 4; q++) acc[mt][nt][q] = 0.f;

    // load mappings
    // A: 1024 float4 units: row = t>>3 (0..127), q = t&7
    // B: 1024 uint4 units: sel = t>>9, row = (t&511)>>2, c = t&3
    const int a_row[4] = { (tid + 0) >> 3, (tid + 256) >> 3, (tid + 512) >> 3, (tid + 768) >> 3 };
    const int a_q = tid & 7;

    // --- prologue: stage 0 directly to smem ---
    {
        const int k0 = 0;
#pragma unroll
        for (int i = 0; i < 4; i++) {
            const int row = a_row[i];
            float4 f = make_float4(0.f, 0.f, 0.f, 0.f);
            if (m0 + row < M)
                f = *reinterpret_cast<const float4*>(&A[(size_t)(m0 + row) * KDIM + k0 + a_q * 4]);
            float hx = __bfloat162float(__float2bfloat16(f.x));
            float hy = __bfloat162float(__float2bfloat16(f.y));
            float hz = __bfloat162float(__float2bfloat16(f.z));
            float hw = __bfloat162float(__float2bfloat16(f.w));
            const int wbase = row * WPR + a_q * 2;
            smw[A_HI + wbase + 0] = pack_bf16(f.x, f.y);
            smw[A_HI + wbase + 1] = pack_bf16(f.z, f.w);
            smw[A_LO + wbase + 0] = pack_bf16(f.x - hx, f.y - hy);
            smw[A_LO + wbase + 1] = pack_bf16(f.z - hz, f.w - hw);
        }
#pragma unroll
        for (int i = 0; i < 4; i++) {
            const int t = tid + i * 256;
            const int sel = t >> 9, tt = t & 511;
            const int row = tt >> 2, c = tt & 3;
            const __nv_bfloat16* src = (sel ? Bl : Bh) + (size_t)(n0 + row) * KDIM + k0 + c * 8;
            uint4 v = *reinterpret_cast<const uint4*>(src);
            *reinterpret_cast<uint4*>(&smw[(sel ? B_LO : B_HI) + row * WPR + c * 4]) = v;
        }
    }
    __syncthreads();

    const int ntiles = KDIM / KC;       // 8
    int buf = 0;

    for (int kt = 0; kt < ntiles; kt++) {
        const bool more = (kt + 1 < ntiles);
        float4 pa[4];
        uint4 pb[4];
        if (more) {
            const int k0 = (kt + 1) * KC;
#pragma unroll
            for (int i = 0; i < 4; i++) {
                const int row = a_row[i];
                pa[i] = make_float4(0.f, 0.f, 0.f, 0.f);
                if (m0 + row < M)
                    pa[i] = *reinterpret_cast<const float4*>(&A[(size_t)(m0 + row) * KDIM + k0 + a_q * 4]);
            }
#pragma unroll
            for (int i = 0; i < 4; i++) {
                const int t = tid + i * 256;
                const int sel = t >> 9, tt = t & 511;
                const int row = tt >> 2, c = tt & 3;
                const __nv_bfloat16* src = (sel ? Bl : Bh) + (size_t)(n0 + row) * KDIM + k0 + c * 8;
                pb[i] = *reinterpret_cast<const uint4*>(src);
            }
        }

        // ---- compute current stage ----
        const int Sb = buf * STAGE_WORDS;
#pragma unroll
        for (int kk = 0; kk < 2; kk++) {
            uint32_t bh[8][2], bl[8][2];
#pragma unroll
            for (int nt = 0; nt < 8; nt++) {
                const int rb = wn * 64 + nt * 8 + g;
                const int w0 = Sb + rb * WPR + kk * 8 + tig;
                bh[nt][0] = smw[B_HI + w0];
                bh[nt][1] = smw[B_HI + w0 + 4];
                bl[nt][0] = smw[B_LO + w0];
                bl[nt][1] = smw[B_LO + w0 + 4];
            }
            uint32_t ah[2][4], al[2][4];
#pragma unroll
            for (int mt = 0; mt < 2; mt++) {
                const int ra = wm * 32 + mt * 16 + g;
                const int w0 = Sb + ra * WPR + kk * 8 + tig;
                ah[mt][0] = smw[A_HI + w0];
                ah[mt][1] = smw[A_HI + w0 + 8 * WPR];
                ah[mt][2] = smw[A_HI + w0 + 4];
                ah[mt][3] = smw[A_HI + w0 + 8 * WPR + 4];
                al[mt][0] = smw[A_LO + w0];
                al[mt][1] = smw[A_LO + w0 + 8 * WPR];
                al[mt][2] = smw[A_LO + w0 + 4];
                al[mt][3] = smw[A_LO + w0 + 8 * WPR + 4];
            }
#pragma unroll
            for (int mt = 0; mt < 2; mt++)
#pragma unroll
                for (int nt = 0; nt < 8; nt++) {
                    mma_bf16(acc[mt][nt], ah[mt][0], ah[mt][1], ah[mt][2], ah[mt][3],
                             bh[nt][0], bh[nt][1]);
                    mma_bf16(acc[mt][nt], ah[mt][0], ah[mt][1], ah[mt][2], ah[mt][3],
                             bl[nt][0], bl[nt][1]);
                    mma_bf16(acc[mt][nt], al[mt][0], al[mt][1], al[mt][2], al[mt][3],
                             bh[nt][0], bh[nt][1]);
                }
        }

        if (more) {
            const int nb = buf ^ 1;
            const int Sn = nb * STAGE_WORDS;
#pragma unroll
            for (int i = 0; i < 4; i++) {
                const int row = a_row[i];
                float4 f = pa[i];
                float hx = __bfloat162float(__float2bfloat16(f.x));
                float hy = __bfloat162float(__float2bfloat16(f.y));
                float hz = __bfloat162float(__float2bfloat16(f.z));
                float hw = __bfloat162float(__float2bfloat16(f.w));
                const int wbase = Sn + row * WPR + a_q * 2;
                smw[A_HI + wbase + 0] = pack_bf16(f.x, f.y);
                smw[A_HI + wbase + 1] = pack_bf16(f.z, f.w);
                smw[A_LO + wbase + 0] = pack_bf16(f.x - hx, f.y - hy);
                smw[A_LO + wbase + 1] = pack_bf16(f.z - hz, f.w - hw);
            }
#pragma unroll
            for (int i = 0; i < 4; i++) {
                const int t = tid + i * 256;
                const int sel = t >> 9, tt = t & 511;
                const int row = tt >> 2, c = tt & 3;
                *reinterpret_cast<uint4*>(&smw[Sn + (sel ? B_LO : B_HI) + row * WPR + c * 4]) = pb[i];
            }
            __syncthreads();
            buf = nb;
        }
    }

    // ---- epilogue ----
#pragma unroll
    for (int mt = 0; mt < 2; mt++) {
        const int r0 = m0 + wm * 32 + mt * 16 + g;
        const int r1 = r0 + 8;
#pragma unroll
        for (int nt = 0; nt < 8; nt++) {
            const int cloc = wn * 64 + nt * 8 + tig * 2;
            const int col = n0 + cloc;
            const float b0 = s_bias[cloc], b1 = s_bias[cloc + 1];
            if (r0 < M) {
                float2 v = make_float2(acc[mt][nt][0] + b0, acc[mt][nt][1] + b1);
                if (resid) {
                    const float2 rv = *reinterpret_cast<const float2*>(&resid[(size_t)r0 * Ntot + col]);
                    v.x += rv.x; v.y += rv.y;
                }
                *reinterpret_cast<float2*>(&C[(size_t)r0 * Ntot + col]) = v;
            }
            if (r1 < M) {
                float2 v = make_float2(acc[mt][nt][2] + b0, acc[mt][nt][3] + b1);
                if (resid) {
                    const float2 rv = *reinterpret_cast<const float2*>(&resid[(size_t)r1 * Ntot + col]);
                    v.x += rv.x; v.y += rv.y;
                }
                *reinterpret_cast<float2*>(&C[(size_t)r1 * Ntot + col]) = v;
            }
        }
    }
}

// ---------------- sampling kernel ----------------
__global__ __launch_bounds__(256)
void msda_sample_kernel(const float* __restrict__ rp)
{
    const int bq = blockIdx.x;
    const int b = bq / NQ;
    const int tid = threadIdx.x;

    __shared__ float s_aw[128];
    __shared__ int   s_pos[128][4];
    __shared__ float s_wt[128][4];

    if (tid < 128) s_aw[tid] = g_aw[(size_t)bq * 128 + tid];
    __syncthreads();

    if (tid < HEADS) {
        const int base = tid * 16;
        float mx = -1e30f;
#pragma unroll
        for (int i = 0; i < 16; i++) mx = fmaxf(mx, s_aw[base + i]);
        float e[16];
        float sum = 0.f;
#pragma unroll
        for (int i = 0; i < 16; i++) { e[i] = __expf(s_aw[base + i] - mx); sum += e[i]; }
        float inv = 1.f / sum;
#pragma unroll
        for (int i = 0; i < 16; i++) s_aw[base + i] = e[i] * inv;
    }
    __syncthreads();

    if (tid < 128) {
        const int s = tid;
        const int l = (s >> 2) & 3;
        const float aw = s_aw[s];
        const float offx = g_off[(size_t)bq * 256 + s * 2];
        const float offy = g_off[(size_t)bq * 256 + s * 2 + 1];
        const float rx = rp[((size_t)bq * LEVELS + l) * 2];
        const float ry = rp[((size_t)bq * LEVELS + l) * 2 + 1];
        const int W = c_LW[l], H = c_LH[l], st = c_LS[l];

        const float locx = rx + offx / (float)W;
        const float locy = ry + offy / (float)H;
        const float x = locx * (float)W - 0.5f;
        const float y = locy * (float)H - 0.5f;
        const float x0f = floorf(x), y0f = floorf(y);
        const float lx = x - x0f, ly = y - y0f;
        const int x0 = (int)x0f, y0 = (int)y0f;

#pragma unroll
        for (int cc = 0; cc < 4; cc++) {
            const int dx = cc & 1, dy = cc >> 1;
            const int xi = x0 + dx, yi = y0 + dy;
            const float wx = dx ? lx : (1.f - lx);
            const float wy = dy ? ly : (1.f - ly);
            const bool valid = (xi >= 0) && (xi < W) && (yi >= 0) && (yi < H);
            const int xc = min(max(xi, 0), W - 1);
            const int yc = min(max(yi, 0), H - 1);
            s_pos[s][cc] = st + yc * W + xc;
            s_wt[s][cc] = valid ? (wx * wy * aw) : 0.f;
        }
    }
    __syncthreads();

    const int h = tid >> 5;
    const float* vb = g_v + (size_t)b * NV * EMBED + tid;
    float acc = 0.f;
#pragma unroll
    for (int i = 0; i < 16; i++) {
        const int s = h * 16 + i;
#pragma unroll
        for (int cc = 0; cc < 4; cc++) {
            acc = fmaf(s_wt[s][cc], __ldg(vb + (size_t)s_pos[s][cc] * EMBED), acc);
        }
    }
    g_attn[(size_t)bq * EMBED + tid] = acc;
}

// ---------------- launch ----------------
extern "C" void kernel_launch(void* const* d_in, const int* in_sizes, int n_in,
                              void* d_out, int out_size)
{
    const float* query  = (const float*)d_in[0];
    const float* value  = (const float*)d_in[1];
    const float* rp     = (const float*)d_in[2];
    const float* W_off  = (const float*)d_in[4];
    const float* b_off  = (const float*)d_in[5];
    const float* W_attn = (const float*)d_in[6];
    const float* b_attn = (const float*)d_in[7];
    const float* W_v    = (const float*)d_in[8];
    const float* b_v    = (const float*)d_in[9];
    const float* W_out  = (const float*)d_in[10];
    const float* b_out  = (const float*)d_in[11];
    float* out = (float*)d_out;

    float *pv, *poff, *paw, *pattn;
    cudaGetSymbolAddress((void**)&pv,    g_v);
    cudaGetSymbolAddress((void**)&poff,  g_off);
    cudaGetSymbolAddress((void**)&paw,   g_aw);
    cudaGetSymbolAddress((void**)&pattn, g_attn);

    __nv_bfloat16 *bvh, *bvl, *boh, *bol, *bah, *bal, *buh, *bul;
    cudaGetSymbolAddress((void**)&bvh, g_Bvh); cudaGetSymbolAddress((void**)&bvl, g_Bvl);
    cudaGetSymbolAddress((void**)&boh, g_Boh); cudaGetSymbolAddress((void**)&bol, g_Bol);
    cudaGetSymbolAddress((void**)&bah, g_Bah); cudaGetSymbolAddress((void**)&bal, g_Bal);
    cudaGetSymbolAddress((void**)&buh, g_Buh); cudaGetSymbolAddress((void**)&bul, g_Bul);

    cudaFuncSetAttribute(mma_gemm_kernel,
                         cudaFuncAttributeMaxDynamicSharedMemorySize, DSMEM_BYTES);

    conv_w_kernel<<<(KDIM * 256 + 255) / 256, 256>>>(W_v,    bvh, bvl, 256);
    conv_w_kernel<<<(KDIM * 256 + 255) / 256, 256>>>(W_off,  boh, bol, 256);
    conv_w_kernel<<<(KDIM * 128 + 255) / 256, 256>>>(W_attn, bah, bal, 128);
    conv_w_kernel<<<(KDIM * 256 + 255) / 256, 256>>>(W_out,  buh, bul, 256);

    const int Mv = BS * NV;
    {   // value projection
        dim3 grid(2, (Mv + 127) / 128);
        mma_gemm_kernel<<<grid, 256, DSMEM_BYTES>>>(value, bvh, bvl, b_v, nullptr, pv, Mv, 256);
    }
    {   // sampling offsets
        dim3 grid(2, (NBQ + 127) / 128);
        mma_gemm_kernel<<<grid, 256, DSMEM_BYTES>>>(query, boh, bol, b_off, nullptr, poff, NBQ, 256);
    }
    {   // attention logits
        dim3 grid(1, (NBQ + 127) / 128);
        mma_gemm_kernel<<<grid, 256, DSMEM_BYTES>>>(query, bah, bal, b_attn, nullptr, paw, NBQ, 128);
    }
    msda_sample_kernel<<<NBQ, 256>>>(rp);
    {   // output projection + residual
        dim3 grid(2, (NBQ + 127) / 128);
        mma_gemm_kernel<<<grid, 256, DSMEM_BYTES>>>(pattn, buh, bul, b_out, query, out, NBQ, 256);
    }
}

// round 6
// speedup vs baseline: 2.2207x; 1.1191x over previous
#include <cuda_runtime.h>
#include <cuda_bf16.h>
#include <cuda_fp16.h>
#include <cstdint>

// ---------------- problem constants ----------------
#define BS      8
#define NQ      900
#define EMBED   256
#define HEADS   8
#define LEVELS  4
#define POINTS  4
#define NV      13294
#define NBQ     (BS * NQ)      // 7200
#define KDIM    256

__device__ __constant__ int c_LH[4] = {100, 50, 25, 13};
__device__ __constant__ int c_LW[4] = {100, 50, 25, 13};
__device__ __constant__ int c_LS[4] = {0, 10000, 12500, 13125};

// ---------------- scratch ----------------
__device__ __half g_vh[(size_t)BS * NV * EMBED];   // projected value, fp16 (~54 MB)
__device__ float g_off[(size_t)NBQ * 256];
__device__ float g_aw[(size_t)NBQ * 128];
__device__ float g_attn[(size_t)NBQ * EMBED];

// pre-converted weights as MMA "B" operand: [N, K] row-major, bf16 hi/lo
__device__ __nv_bfloat16 g_Bvh[256 * 256], g_Bvl[256 * 256];
__device__ __nv_bfloat16 g_Boh[256 * 256], g_Bol[256 * 256];
__device__ __nv_bfloat16 g_Bah[128 * 256], g_Bal[128 * 256];
__device__ __nv_bfloat16 g_Buh[256 * 256], g_Bul[256 * 256];

// ---------------- helpers ----------------
__device__ __forceinline__ uint32_t pack_bf16(float x, float y) {
    __nv_bfloat162 h = __floats2bfloat162_rn(x, y);
    return *reinterpret_cast<uint32_t*>(&h);
}

__device__ __forceinline__ void mma_bf16(float d[4],
                                         uint32_t a0, uint32_t a1, uint32_t a2, uint32_t a3,
                                         uint32_t b0, uint32_t b1) {
    asm volatile(
        "mma.sync.aligned.m16n8k16.row.col.f32.bf16.bf16.f32 "
        "{%0,%1,%2,%3}, {%4,%5,%6,%7}, {%8,%9}, {%0,%1,%2,%3};"
        : "+f"(d[0]), "+f"(d[1]), "+f"(d[2]), "+f"(d[3])
        : "r"(a0), "r"(a1), "r"(a2), "r"(a3), "r"(b0), "r"(b1));
}

// ---------------- fused weight conversion: all four W[K,N] -> B[N,K] hi/lo --
__global__ void conv_all_kernel(const float* __restrict__ Wv,
                                const float* __restrict__ Woff,
                                const float* __restrict__ Wattn,
                                const float* __restrict__ Wout,
                                __nv_bfloat16* __restrict__ Bvh, __nv_bfloat16* __restrict__ Bvl,
                                __nv_bfloat16* __restrict__ Boh, __nv_bfloat16* __restrict__ Bol,
                                __nv_bfloat16* __restrict__ Bah, __nv_bfloat16* __restrict__ Bal,
                                __nv_bfloat16* __restrict__ Buh, __nv_bfloat16* __restrict__ Bul)
{
    int i = blockIdx.x * 256 + threadIdx.x;   // 0 .. 229375
    const float* W; __nv_bfloat16 *Bh, *Bl; int N, j;
    if (i < 65536)        { W = Wv;    Bh = Bvh; Bl = Bvl; N = 256; j = i; }
    else if (i < 131072)  { W = Woff;  Bh = Boh; Bl = Bol; N = 256; j = i - 65536; }
    else if (i < 163840)  { W = Wattn; Bh = Bah; Bl = Bal; N = 128; j = i - 131072; }
    else if (i < 229376)  { W = Wout;  Bh = Buh; Bl = Bul; N = 256; j = i - 163840; }
    else return;
    int k = j / N, n = j % N;
    float x = W[j];
    __nv_bfloat16 hb = __float2bfloat16(x);
    float lo = x - __bfloat162float(hb);
    Bh[(size_t)n * KDIM + k] = hb;
    Bl[(size_t)n * KDIM + k] = __float2bfloat16(lo);
}

// ---------------- HMMA GEMM: C[M,Ntot] = A[M,256] @ B[N,256]^T + bias (+resid)
// CTA 128x128, KC=32 double-buffered, bf16x3 split, mma.sync m16n8k16.
// If Ch != nullptr, output is written as fp16 to Ch instead of fp32 to C.
#define KC 32
#define WPR 20
#define A_HI 0
#define A_LO (128 * WPR)
#define B_HI (2 * 128 * WPR)
#define B_LO (3 * 128 * WPR)
#define STAGE_WORDS (4 * 128 * WPR)
#define DSMEM_BYTES (2 * STAGE_WORDS * 4)

__global__ __launch_bounds__(256, 1)
void mma_gemm_kernel(const float* __restrict__ A,
                     const __nv_bfloat16* __restrict__ Bh,
                     const __nv_bfloat16* __restrict__ Bl,
                     const float* __restrict__ bias,
                     const float* __restrict__ resid,
                     float* __restrict__ C,
                     __half* __restrict__ Ch,
                     int M, int Ntot)
{
    extern __shared__ uint32_t smw[];
    __shared__ float s_bias[128];

    const int tid = threadIdx.x;
    const int wid = tid >> 5;
    const int lane = tid & 31;
    const int g = lane >> 2;
    const int tig = lane & 3;
    const int wm = wid & 3;
    const int wn = wid >> 2;
    const int m0 = blockIdx.y * 128;
    const int n0 = blockIdx.x * 128;

    if (tid < 128) s_bias[tid] = bias[n0 + tid];

    float acc[2][8][4];
#pragma unroll
    for (int mt = 0; mt < 2; mt++)
#pragma unroll
        for (int nt = 0; nt < 8; nt++)
#pragma unroll
            for (int q = 0; q < 4; q++) acc[mt][nt][q] = 0.f;

    const int a_row[4] = { (tid + 0) >> 3, (tid + 256) >> 3, (tid + 512) >> 3, (tid + 768) >> 3 };
    const int a_q = tid & 7;

    // --- prologue: stage 0 directly to smem ---
    {
        const int k0 = 0;
#pragma unroll
        for (int i = 0; i < 4; i++) {
            const int row = a_row[i];
            float4 f = make_float4(0.f, 0.f, 0.f, 0.f);
            if (m0 + row < M)
                f = *reinterpret_cast<const float4*>(&A[(size_t)(m0 + row) * KDIM + k0 + a_q * 4]);
            float hx = __bfloat162float(__float2bfloat16(f.x));
            float hy = __bfloat162float(__float2bfloat16(f.y));
            float hz = __bfloat162float(__float2bfloat16(f.z));
            float hw = __bfloat162float(__float2bfloat16(f.w));
            const int wbase = row * WPR + a_q * 2;
            smw[A_HI + wbase + 0] = pack_bf16(f.x, f.y);
            smw[A_HI + wbase + 1] = pack_bf16(f.z, f.w);
            smw[A_LO + wbase + 0] = pack_bf16(f.x - hx, f.y - hy);
            smw[A_LO + wbase + 1] = pack_bf16(f.z - hz, f.w - hw);
        }
#pragma unroll
        for (int i = 0; i < 4; i++) {
            const int t = tid + i * 256;
            const int sel = t >> 9, tt = t & 511;
            const int row = tt >> 2, c = tt & 3;
            const __nv_bfloat16* src = (sel ? Bl : Bh) + (size_t)(n0 + row) * KDIM + k0 + c * 8;
            uint4 v = *reinterpret_cast<const uint4*>(src);
            *reinterpret_cast<uint4*>(&smw[(sel ? B_LO : B_HI) + row * WPR + c * 4]) = v;
        }
    }
    __syncthreads();

    const int ntiles = KDIM / KC;
    int buf = 0;

    for (int kt = 0; kt < ntiles; kt++) {
        const bool more = (kt + 1 < ntiles);
        float4 pa[4];
        uint4 pb[4];
        if (more) {
            const int k0 = (kt + 1) * KC;
#pragma unroll
            for (int i = 0; i < 4; i++) {
                const int row = a_row[i];
                pa[i] = make_float4(0.f, 0.f, 0.f, 0.f);
                if (m0 + row < M)
                    pa[i] = *reinterpret_cast<const float4*>(&A[(size_t)(m0 + row) * KDIM + k0 + a_q * 4]);
            }
#pragma unroll
            for (int i = 0; i < 4; i++) {
                const int t = tid + i * 256;
                const int sel = t >> 9, tt = t & 511;
                const int row = tt >> 2, c = tt & 3;
                const __nv_bfloat16* src = (sel ? Bl : Bh) + (size_t)(n0 + row) * KDIM + k0 + c * 8;
                pb[i] = *reinterpret_cast<const uint4*>(src);
            }
        }

        const int Sb = buf * STAGE_WORDS;
#pragma unroll
        for (int kk = 0; kk < 2; kk++) {
            uint32_t bh[8][2], bl[8][2];
#pragma unroll
            for (int nt = 0; nt < 8; nt++) {
                const int rb = wn * 64 + nt * 8 + g;
                const int w0 = Sb + rb * WPR + kk * 8 + tig;
                bh[nt][0] = smw[B_HI + w0];
                bh[nt][1] = smw[B_HI + w0 + 4];
                bl[nt][0] = smw[B_LO + w0];
                bl[nt][1] = smw[B_LO + w0 + 4];
            }
            uint32_t ah[2][4], al[2][4];
#pragma unroll
            for (int mt = 0; mt < 2; mt++) {
                const int ra = wm * 32 + mt * 16 + g;
                const int w0 = Sb + ra * WPR + kk * 8 + tig;
                ah[mt][0] = smw[A_HI + w0];
                ah[mt][1] = smw[A_HI + w0 + 8 * WPR];
                ah[mt][2] = smw[A_HI + w0 + 4];
                ah[mt][3] = smw[A_HI + w0 + 8 * WPR + 4];
                al[mt][0] = smw[A_LO + w0];
                al[mt][1] = smw[A_LO + w0 + 8 * WPR];
                al[mt][2] = smw[A_LO + w0 + 4];
                al[mt][3] = smw[A_LO + w0 + 8 * WPR + 4];
            }
#pragma unroll
            for (int mt = 0; mt < 2; mt++)
#pragma unroll
                for (int nt = 0; nt < 8; nt++) {
                    mma_bf16(acc[mt][nt], ah[mt][0], ah[mt][1], ah[mt][2], ah[mt][3],
                             bh[nt][0], bh[nt][1]);
                    mma_bf16(acc[mt][nt], ah[mt][0], ah[mt][1], ah[mt][2], ah[mt][3],
                             bl[nt][0], bl[nt][1]);
                    mma_bf16(acc[mt][nt], al[mt][0], al[mt][1], al[mt][2], al[mt][3],
                             bh[nt][0], bh[nt][1]);
                }
        }

        if (more) {
            const int nb = buf ^ 1;
            const int Sn = nb * STAGE_WORDS;
#pragma unroll
            for (int i = 0; i < 4; i++) {
                const int row = a_row[i];
                float4 f = pa[i];
                float hx = __bfloat162float(__float2bfloat16(f.x));
                float hy = __bfloat162float(__float2bfloat16(f.y));
                float hz = __bfloat162float(__float2bfloat16(f.z));
                float hw = __bfloat162float(__float2bfloat16(f.w));
                const int wbase = Sn + row * WPR + a_q * 2;
                smw[A_HI + wbase + 0] = pack_bf16(f.x, f.y);
                smw[A_HI + wbase + 1] = pack_bf16(f.z, f.w);
                smw[A_LO + wbase + 0] = pack_bf16(f.x - hx, f.y - hy);
                smw[A_LO + wbase + 1] = pack_bf16(f.z - hz, f.w - hw);
            }
#pragma unroll
            for (int i = 0; i < 4; i++) {
                const int t = tid + i * 256;
                const int sel = t >> 9, tt = t & 511;
                const int row = tt >> 2, c = tt & 3;
                *reinterpret_cast<uint4*>(&smw[Sn + (sel ? B_LO : B_HI) + row * WPR + c * 4]) = pb[i];
            }
            __syncthreads();
            buf = nb;
        }
    }

    // ---- epilogue ----
#pragma unroll
    for (int mt = 0; mt < 2; mt++) {
        const int r0 = m0 + wm * 32 + mt * 16 + g;
        const int r1 = r0 + 8;
#pragma unroll
        for (int nt = 0; nt < 8; nt++) {
            const int cloc = wn * 64 + nt * 8 + tig * 2;
            const int col = n0 + cloc;
            const float b0 = s_bias[cloc], b1 = s_bias[cloc + 1];
            float2 v0 = make_float2(acc[mt][nt][0] + b0, acc[mt][nt][1] + b1);
            float2 v1 = make_float2(acc[mt][nt][2] + b0, acc[mt][nt][3] + b1);
            if (resid) {
                if (r0 < M) {
                    const float2 rv = *reinterpret_cast<const float2*>(&resid[(size_t)r0 * Ntot + col]);
                    v0.x += rv.x; v0.y += rv.y;
                }
                if (r1 < M) {
                    const float2 rv = *reinterpret_cast<const float2*>(&resid[(size_t)r1 * Ntot + col]);
                    v1.x += rv.x; v1.y += rv.y;
                }
            }
            if (Ch) {
                if (r0 < M)
                    *reinterpret_cast<__half2*>(&Ch[(size_t)r0 * Ntot + col]) = __floats2half2_rn(v0.x, v0.y);
                if (r1 < M)
                    *reinterpret_cast<__half2*>(&Ch[(size_t)r1 * Ntot + col]) = __floats2half2_rn(v1.x, v1.y);
            } else {
                if (r0 < M) *reinterpret_cast<float2*>(&C[(size_t)r0 * Ntot + col]) = v0;
                if (r1 < M) *reinterpret_cast<float2*>(&C[(size_t)r1 * Ntot + col]) = v1;
            }
        }
    }
}

// ---------------- sampling kernel: 2 queries/block, half2 gathers ----------
__global__ __launch_bounds__(256)
void msda_sample_kernel(const float* __restrict__ rp)
{
    const int tid = threadIdx.x;
    const int qi = tid >> 7;                 // which of the 2 queries
    const int tq = tid & 127;                // thread within query
    const int q = blockIdx.x * 2 + qi;       // 0..NBQ-1
    const int b = q / NQ;

    __shared__ float s_aw[2][128];
    __shared__ int   s_pos[2][128][4];
    __shared__ float s_wt[2][128][4];

    s_aw[qi][tq] = g_aw[(size_t)q * 128 + tq];
    __syncthreads();

    // per-head softmax over 16: 16 threads (2 queries x 8 heads)
    if (tid < 16) {
        const int sq = tid >> 3, h = tid & 7;
        float* aw = &s_aw[sq][h * 16];
        float mx = -1e30f;
#pragma unroll
        for (int i = 0; i < 16; i++) mx = fmaxf(mx, aw[i]);
        float e[16];
        float sum = 0.f;
#pragma unroll
        for (int i = 0; i < 16; i++) { e[i] = __expf(aw[i] - mx); sum += e[i]; }
        float inv = 1.f / sum;
#pragma unroll
        for (int i = 0; i < 16; i++) aw[i] = e[i] * inv;
    }
    __syncthreads();

    // corner precompute: 256 threads handle 2x128 samples
    {
        const int s = tq;
        const int l = (s >> 2) & 3;
        const float aw = s_aw[qi][s];
        const float offx = g_off[(size_t)q * 256 + s * 2];
        const float offy = g_off[(size_t)q * 256 + s * 2 + 1];
        const float rx = rp[((size_t)q * LEVELS + l) * 2];
        const float ry = rp[((size_t)q * LEVELS + l) * 2 + 1];
        const int W = c_LW[l], H = c_LH[l], st = c_LS[l];

        const float locx = rx + offx / (float)W;
        const float locy = ry + offy / (float)H;
        const float x = locx * (float)W - 0.5f;
        const float y = locy * (float)H - 0.5f;
        const float x0f = floorf(x), y0f = floorf(y);
        const float lx = x - x0f, ly = y - y0f;
        const int x0 = (int)x0f, y0 = (int)y0f;

#pragma unroll
        for (int cc = 0; cc < 4; cc++) {
            const int dx = cc & 1, dy = cc >> 1;
            const int xi = x0 + dx, yi = y0 + dy;
            const float wx = dx ? lx : (1.f - lx);
            const float wy = dy ? ly : (1.f - ly);
            const bool valid = (xi >= 0) && (xi < W) && (yi >= 0) && (yi < H);
            const int xc = min(max(xi, 0), W - 1);
            const int yc = min(max(yi, 0), H - 1);
            s_pos[qi][s][cc] = st + yc * W + xc;
            s_wt[qi][s][cc] = valid ? (wx * wy * aw) : 0.f;
        }
    }
    __syncthreads();

    // gather: thread = (query, head, channel-pair); half2 loads
    const int h = tq >> 4;
    const int d2 = tq & 15;
    const int ch = h * 32 + d2 * 2;
    const __half* vb = g_vh + (size_t)b * NV * EMBED + ch;
    float2 acc = make_float2(0.f, 0.f);
#pragma unroll
    for (int i = 0; i < 16; i++) {
        const int s = h * 16 + i;
#pragma unroll
        for (int cc = 0; cc < 4; cc++) {
            const float w = s_wt[qi][s][cc];
            const __half2 hv = *reinterpret_cast<const __half2*>(vb + (size_t)s_pos[qi][s][cc] * EMBED);
            const float2 f = __half22float2(hv);
            acc.x = fmaf(w, f.x, acc.x);
            acc.y = fmaf(w, f.y, acc.y);
        }
    }
    *reinterpret_cast<float2*>(&g_attn[(size_t)q * EMBED + ch]) = acc;
}

// ---------------- launch ----------------
extern "C" void kernel_launch(void* const* d_in, const int* in_sizes, int n_in,
                              void* d_out, int out_size)
{
    const float* query  = (const float*)d_in[0];
    const float* value  = (const float*)d_in[1];
    const float* rp     = (const float*)d_in[2];
    const float* W_off  = (const float*)d_in[4];
    const float* b_off  = (const float*)d_in[5];
    const float* W_attn = (const float*)d_in[6];
    const float* b_attn = (const float*)d_in[7];
    const float* W_v    = (const float*)d_in[8];
    const float* b_v    = (const float*)d_in[9];
    const float* W_out  = (const float*)d_in[10];
    const float* b_out  = (const float*)d_in[11];
    float* out = (float*)d_out;

    float *poff, *paw, *pattn;
    __half* pvh;
    cudaGetSymbolAddress((void**)&pvh,   g_vh);
    cudaGetSymbolAddress((void**)&poff,  g_off);
    cudaGetSymbolAddress((void**)&paw,   g_aw);
    cudaGetSymbolAddress((void**)&pattn, g_attn);

    __nv_bfloat16 *bvh, *bvl, *boh, *bol, *bah, *bal, *buh, *bul;
    cudaGetSymbolAddress((void**)&bvh, g_Bvh); cudaGetSymbolAddress((void**)&bvl, g_Bvl);
    cudaGetSymbolAddress((void**)&boh, g_Boh); cudaGetSymbolAddress((void**)&bol, g_Bol);
    cudaGetSymbolAddress((void**)&bah, g_Bah); cudaGetSymbolAddress((void**)&bal, g_Bal);
    cudaGetSymbolAddress((void**)&buh, g_Buh); cudaGetSymbolAddress((void**)&bul, g_Bul);

    cudaFuncSetAttribute(mma_gemm_kernel,
                         cudaFuncAttributeMaxDynamicSharedMemorySize, DSMEM_BYTES);

    conv_all_kernel<<<896, 256>>>(W_v, W_off, W_attn, W_out,
                                  bvh, bvl, boh, bol, bah, bal, buh, bul);

    const int Mv = BS * NV;
    {   // value projection -> fp16
        dim3 grid(2, (Mv + 127) / 128);
        mma_gemm_kernel<<<grid, 256, DSMEM_BYTES>>>(value, bvh, bvl, b_v, nullptr,
                                                    nullptr, pvh, Mv, 256);
    }
    {   // sampling offsets
        dim3 grid(2, (NBQ + 127) / 128);
        mma_gemm_kernel<<<grid, 256, DSMEM_BYTES>>>(query, boh, bol, b_off, nullptr,
                                                    poff, nullptr, NBQ, 256);
    }
    {   // attention logits
        dim3 grid(1, (NBQ + 127) / 128);
        mma_gemm_kernel<<<grid, 256, DSMEM_BYTES>>>(query, bah, bal, b_attn, nullptr,
                                                    paw, nullptr, NBQ, 128);
    }
    msda_sample_kernel<<<NBQ / 2, 256>>>(rp);
    {   // output projection + residual
        dim3 grid(2, (NBQ + 127) / 128);
        mma_gemm_kernel<<<grid, 256, DSMEM_BYTES>>>(pattn, buh, bul, b_out, query,
                                                    out, nullptr, NBQ, 256);
    }
}

// round 7
// speedup vs baseline: 2.3507x; 1.0586x over previous
#include <cuda_runtime.h>
#include <cuda_bf16.h>
#include <cuda_fp16.h>
#include <cstdint>

// ---------------- problem constants ----------------
#define BS      8
#define NQ      900
#define EMBED   256
#define HEADS   8
#define LEVELS  4
#define POINTS  4
#define NV      13294
#define NBQ     (BS * NQ)      // 7200
#define KDIM    256

__device__ __constant__ int c_LH[4] = {100, 50, 25, 13};
__device__ __constant__ int c_LW[4] = {100, 50, 25, 13};
__device__ __constant__ int c_LS[4] = {0, 10000, 12500, 13125};

// ---------------- scratch ----------------
__device__ __half g_vh[(size_t)BS * NV * EMBED];
__device__ float g_off[(size_t)NBQ * 256];
__device__ float g_aw[(size_t)NBQ * 128];
__device__ float g_attn[(size_t)NBQ * EMBED];

__device__ __nv_bfloat16 g_Bvh[256 * 256], g_Bvl[256 * 256];
__device__ __nv_bfloat16 g_Boh[256 * 256], g_Bol[256 * 256];
__device__ __nv_bfloat16 g_Bah[128 * 256], g_Bal[128 * 256];
__device__ __nv_bfloat16 g_Buh[256 * 256], g_Bul[256 * 256];

// ---------------- helpers ----------------
__device__ __forceinline__ uint32_t smem_u32(const void* p) {
    uint32_t a;
    asm("{ .reg .u64 t; cvta.to.shared.u64 t, %1; cvt.u32.u64 %0, t; }" : "=r"(a) : "l"(p));
    return a;
}
__device__ __forceinline__ uint32_t pack_bf16(float x, float y) {
    __nv_bfloat162 h = __floats2bfloat162_rn(x, y);
    return *reinterpret_cast<uint32_t*>(&h);
}
__device__ __forceinline__ void mma_bf16(float d[4],
                                         uint32_t a0, uint32_t a1, uint32_t a2, uint32_t a3,
                                         uint32_t b0, uint32_t b1) {
    asm volatile(
        "mma.sync.aligned.m16n8k16.row.col.f32.bf16.bf16.f32 "
        "{%0,%1,%2,%3}, {%4,%5,%6,%7}, {%8,%9}, {%0,%1,%2,%3};"
        : "+f"(d[0]), "+f"(d[1]), "+f"(d[2]), "+f"(d[3])
        : "r"(a0), "r"(a1), "r"(a2), "r"(a3), "r"(b0), "r"(b1));
}
__device__ __forceinline__ void ldsm_x4(uint32_t& r0, uint32_t& r1, uint32_t& r2, uint32_t& r3,
                                        uint32_t addr) {
    asm volatile("ldmatrix.sync.aligned.m8n8.x4.shared.b16 {%0,%1,%2,%3}, [%4];"
                 : "=r"(r0), "=r"(r1), "=r"(r2), "=r"(r3) : "r"(addr));
}
__device__ __forceinline__ void cp_async16(uint32_t saddr, const void* gaddr) {
    asm volatile("cp.async.ca.shared.global [%0], [%1], 16;" :: "r"(saddr), "l"(gaddr));
}

// ---------------- fused weight conversion ----------------
__global__ void conv_all_kernel(const float* __restrict__ Wv,
                                const float* __restrict__ Woff,
                                const float* __restrict__ Wattn,
                                const float* __restrict__ Wout,
                                __nv_bfloat16* __restrict__ Bvh, __nv_bfloat16* __restrict__ Bvl,
                                __nv_bfloat16* __restrict__ Boh, __nv_bfloat16* __restrict__ Bol,
                                __nv_bfloat16* __restrict__ Bah, __nv_bfloat16* __restrict__ Bal,
                                __nv_bfloat16* __restrict__ Buh, __nv_bfloat16* __restrict__ Bul)
{
    int i = blockIdx.x * 256 + threadIdx.x;
    const float* W; __nv_bfloat16 *Bh, *Bl; int N, j;
    if (i < 65536)        { W = Wv;    Bh = Bvh; Bl = Bvl; N = 256; j = i; }
    else if (i < 131072)  { W = Woff;  Bh = Boh; Bl = Bol; N = 256; j = i - 65536; }
    else if (i < 163840)  { W = Wattn; Bh = Bah; Bl = Bal; N = 128; j = i - 131072; }
    else if (i < 229376)  { W = Wout;  Bh = Buh; Bl = Bul; N = 256; j = i - 163840; }
    else return;
    int k = j / N, n = j % N;
    float x = W[j];
    __nv_bfloat16 hb = __float2bfloat16(x);
    float lo = x - __bfloat162float(hb);
    Bh[(size_t)n * KDIM + k] = hb;
    Bl[(size_t)n * KDIM + k] = __float2bfloat16(lo);
}

// ---------------- HMMA GEMM: CTA 128x64, warp 32x32, ldmatrix + cp.async ----
// C[M,Ntot] = A[M,256] @ B[N,256]^T + bias (+resid). bf16x3 split, KC=32 x2buf.
#define KC 32
#define ROWB 80                         // bytes per smem row (32 bf16 + 16 pad)
#define A_HI_B 0
#define A_LO_B (128 * ROWB)             // 10240
#define B_HI_B (2 * 128 * ROWB)         // 20480
#define B_LO_B (B_HI_B + 64 * ROWB)     // 25600
#define STAGE_B (B_LO_B + 64 * ROWB)    // 30720
#define DSMEM_BYTES (2 * STAGE_B)       // 61440

__global__ __launch_bounds__(256, 2)
void mma_gemm_kernel(const float* __restrict__ A,
                     const __nv_bfloat16* __restrict__ Bh,
                     const __nv_bfloat16* __restrict__ Bl,
                     const float* __restrict__ bias,
                     const float* __restrict__ resid,
                     float* __restrict__ C,
                     __half* __restrict__ Ch,
                     int M, int Ntot)
{
    extern __shared__ char smemc[];
    __shared__ float s_bias[64];

    const int tid = threadIdx.x;
    const int wid = tid >> 5;
    const int lane = tid & 31;
    const int g = lane >> 2;
    const int tig = lane & 3;
    const int wm = wid & 3;             // 4 warps along M (32 each)
    const int wn = wid >> 2;            // 2 warps along N (32 each)
    const int m0 = blockIdx.y * 128;
    const int n0 = blockIdx.x * 64;

    if (tid < 64) s_bias[tid] = bias[n0 + tid];

    const uint32_t sbase = smem_u32(smemc);

    float acc[2][4][4];
#pragma unroll
    for (int mt = 0; mt < 2; mt++)
#pragma unroll
        for (int nt = 0; nt < 4; nt++)
#pragma unroll
            for (int q = 0; q < 4; q++) acc[mt][nt][q] = 0.f;

    // A fill map: 1024 float4 units, thread handles 4: row = t>>3, q = t&7
    const int a_row[4] = { (tid + 0) >> 3, (tid + 256) >> 3, (tid + 512) >> 3, (tid + 768) >> 3 };
    const int a_q = tid & 7;

    // B cp.async map: 512 16B units, thread handles 2: t = tid, tid+256
    // sel = t>>8, row = (t&255)>>2, c = t&3
    const int b_sel0 = 0, b_row0 = tid >> 2, b_c0 = tid & 3;        // t = tid (<256)
    const int b_row1 = b_row0, b_c1 = b_c0;                          // t = tid+256 -> sel=1

    // ldmatrix per-thread address components
    const int lm_arow = lane & 15;
    const int lm_akoff = (lane >> 4) * 16;
    const int lm_brow = (lane & 7) + ((lane >> 4) << 3);
    const int lm_bkoff = ((lane >> 3) & 1) * 16;

    // --- helper lambdas (inlined) ---
    auto fill_A = [&](int stage, const float4* pa) {
        const uint32_t Sb = sbase + stage * STAGE_B;
#pragma unroll
        for (int i = 0; i < 4; i++) {
            const float4 f = pa[i];
            float hx = __bfloat162float(__float2bfloat16(f.x));
            float hy = __bfloat162float(__float2bfloat16(f.y));
            float hz = __bfloat162float(__float2bfloat16(f.z));
            float hw = __bfloat162float(__float2bfloat16(f.w));
            const uint32_t off = (uint32_t)(a_row[i] * ROWB + a_q * 8);
            *reinterpret_cast<uint2*>(smemc + stage * STAGE_B + A_HI_B + off) =
                make_uint2(pack_bf16(f.x, f.y), pack_bf16(f.z, f.w));
            *reinterpret_cast<uint2*>(smemc + stage * STAGE_B + A_LO_B + off) =
                make_uint2(pack_bf16(f.x - hx, f.y - hy), pack_bf16(f.z - hz, f.w - hw));
        }
        (void)Sb;
    };

    auto issue_B = [&](int stage, int k0) {
        const uint32_t Sb = sbase + stage * STAGE_B;
        // unit 0: hi
        cp_async16(Sb + B_HI_B + b_row0 * ROWB + b_c0 * 16,
                   Bh + (size_t)(n0 + b_row0) * KDIM + k0 + b_c0 * 8);
        // unit 1: lo
        cp_async16(Sb + B_LO_B + b_row1 * ROWB + b_c1 * 16,
                   Bl + (size_t)(n0 + b_row1) * KDIM + k0 + b_c1 * 8);
        asm volatile("cp.async.commit_group;" ::: "memory");
    };

    // --- prologue: stage 0 ---
    {
        issue_B(0, 0);
        float4 pa[4];
#pragma unroll
        for (int i = 0; i < 4; i++) {
            pa[i] = make_float4(0.f, 0.f, 0.f, 0.f);
            if (m0 + a_row[i] < M)
                pa[i] = *reinterpret_cast<const float4*>(&A[(size_t)(m0 + a_row[i]) * KDIM + a_q * 4]);
        }
        fill_A(0, pa);
        asm volatile("cp.async.wait_group 0;" ::: "memory");
    }
    __syncthreads();

    const int ntiles = KDIM / KC;       // 8
    int buf = 0;

    for (int kt = 0; kt < ntiles; kt++) {
        const bool more = (kt + 1 < ntiles);
        float4 pa[4];
        if (more) {
            const int k0 = (kt + 1) * KC;
            issue_B(buf ^ 1, k0);
#pragma unroll
            for (int i = 0; i < 4; i++) {
                pa[i] = make_float4(0.f, 0.f, 0.f, 0.f);
                if (m0 + a_row[i] < M)
                    pa[i] = *reinterpret_cast<const float4*>(&A[(size_t)(m0 + a_row[i]) * KDIM + k0 + a_q * 4]);
            }
        }

        // ---- compute current stage ----
        const uint32_t Sb = sbase + buf * STAGE_B;
#pragma unroll
        for (int kk = 0; kk < 2; kk++) {
            // B fragments: 2 ldmatrix.x4 per matrix (nt pairs)
            uint32_t bh[4][2], bl[4][2];
#pragma unroll
            for (int p = 0; p < 2; p++) {
                const uint32_t baddr = Sb + (uint32_t)((wn * 32 + p * 16 + lm_brow) * ROWB + kk * 32 + lm_bkoff);
                ldsm_x4(bh[2 * p][0], bh[2 * p][1], bh[2 * p + 1][0], bh[2 * p + 1][1],
                        baddr + B_HI_B);
                ldsm_x4(bl[2 * p][0], bl[2 * p][1], bl[2 * p + 1][0], bl[2 * p + 1][1],
                        baddr + B_LO_B);
            }
            // A fragments: 1 ldmatrix.x4 per mt per matrix
            uint32_t ah[2][4], al[2][4];
#pragma unroll
            for (int mt = 0; mt < 2; mt++) {
                const uint32_t aaddr = Sb + (uint32_t)((wm * 32 + mt * 16 + lm_arow) * ROWB + kk * 32 + lm_akoff);
                ldsm_x4(ah[mt][0], ah[mt][1], ah[mt][2], ah[mt][3], aaddr + A_HI_B);
                ldsm_x4(al[mt][0], al[mt][1], al[mt][2], al[mt][3], aaddr + A_LO_B);
            }
#pragma unroll
            for (int mt = 0; mt < 2; mt++)
#pragma unroll
                for (int nt = 0; nt < 4; nt++) {
                    mma_bf16(acc[mt][nt], ah[mt][0], ah[mt][1], ah[mt][2], ah[mt][3],
                             bh[nt][0], bh[nt][1]);
                    mma_bf16(acc[mt][nt], ah[mt][0], ah[mt][1], ah[mt][2], ah[mt][3],
                             bl[nt][0], bl[nt][1]);
                    mma_bf16(acc[mt][nt], al[mt][0], al[mt][1], al[mt][2], al[mt][3],
                             bh[nt][0], bh[nt][1]);
                }
        }

        if (more) {
            fill_A(buf ^ 1, pa);
            asm volatile("cp.async.wait_group 0;" ::: "memory");
            __syncthreads();
            buf ^= 1;
        }
    }

    // ---- epilogue ----
#pragma unroll
    for (int mt = 0; mt < 2; mt++) {
        const int r0 = m0 + wm * 32 + mt * 16 + g;
        const int r1 = r0 + 8;
#pragma unroll
        for (int nt = 0; nt < 4; nt++) {
            const int cloc = wn * 32 + nt * 8 + tig * 2;
            const int col = n0 + cloc;
            const float b0 = s_bias[cloc], b1 = s_bias[cloc + 1];
            float2 v0 = make_float2(acc[mt][nt][0] + b0, acc[mt][nt][1] + b1);
            float2 v1 = make_float2(acc[mt][nt][2] + b0, acc[mt][nt][3] + b1);
            if (resid) {
                if (r0 < M) {
                    const float2 rv = *reinterpret_cast<const float2*>(&resid[(size_t)r0 * Ntot + col]);
                    v0.x += rv.x; v0.y += rv.y;
                }
                if (r1 < M) {
                    const float2 rv = *reinterpret_cast<const float2*>(&resid[(size_t)r1 * Ntot + col]);
                    v1.x += rv.x; v1.y += rv.y;
                }
            }
            if (Ch) {
                if (r0 < M)
                    *reinterpret_cast<__half2*>(&Ch[(size_t)r0 * Ntot + col]) = __floats2half2_rn(v0.x, v0.y);
                if (r1 < M)
                    *reinterpret_cast<__half2*>(&Ch[(size_t)r1 * Ntot + col]) = __floats2half2_rn(v1.x, v1.y);
            } else {
                if (r0 < M) *reinterpret_cast<float2*>(&C[(size_t)r0 * Ntot + col]) = v0;
                if (r1 < M) *reinterpret_cast<float2*>(&C[(size_t)r1 * Ntot + col]) = v1;
            }
        }
    }
}

// ---------------- sampling kernel: 2 queries/block, half2 gathers ----------
__global__ __launch_bounds__(256)
void msda_sample_kernel(const float* __restrict__ rp)
{
    const int tid = threadIdx.x;
    const int qi = tid >> 7;
    const int tq = tid & 127;
    const int q = blockIdx.x * 2 + qi;
    const int b = q / NQ;

    __shared__ float s_aw[2][128];
    __shared__ int   s_pos[2][128][4];
    __shared__ float s_wt[2][128][4];

    s_aw[qi][tq] = g_aw[(size_t)q * 128 + tq];
    __syncthreads();

    if (tid < 16) {
        const int sq = tid >> 3, h = tid & 7;
        float* aw = &s_aw[sq][h * 16];
        float mx = -1e30f;
#pragma unroll
        for (int i = 0; i < 16; i++) mx = fmaxf(mx, aw[i]);
        float e[16];
        float sum = 0.f;
#pragma unroll
        for (int i = 0; i < 16; i++) { e[i] = __expf(aw[i] - mx); sum += e[i]; }
        float inv = 1.f / sum;
#pragma unroll
        for (int i = 0; i < 16; i++) aw[i] = e[i] * inv;
    }
    __syncthreads();

    {
        const int s = tq;
        const int l = (s >> 2) & 3;
        const float aw = s_aw[qi][s];
        const float offx = g_off[(size_t)q * 256 + s * 2];
        const float offy = g_off[(size_t)q * 256 + s * 2 + 1];
        const float rx = rp[((size_t)q * LEVELS + l) * 2];
        const float ry = rp[((size_t)q * LEVELS + l) * 2 + 1];
        const int W = c_LW[l], H = c_LH[l], st = c_LS[l];

        const float locx = rx + offx / (float)W;
        const float locy = ry + offy / (float)H;
        const float x = locx * (float)W - 0.5f;
        const float y = locy * (float)H - 0.5f;
        const float x0f = floorf(x), y0f = floorf(y);
        const float lx = x - x0f, ly = y - y0f;
        const int x0 = (int)x0f, y0 = (int)y0f;

#pragma unroll
        for (int cc = 0; cc < 4; cc++) {
            const int dx = cc & 1, dy = cc >> 1;
            const int xi = x0 + dx, yi = y0 + dy;
            const float wx = dx ? lx : (1.f - lx);
            const float wy = dy ? ly : (1.f - ly);
            const bool valid = (xi >= 0) && (xi < W) && (yi >= 0) && (yi < H);
            const int xc = min(max(xi, 0), W - 1);
            const int yc = min(max(yi, 0), H - 1);
            s_pos[qi][s][cc] = st + yc * W + xc;
            s_wt[qi][s][cc] = valid ? (wx * wy * aw) : 0.f;
        }
    }
    __syncthreads();

    const int h = tq >> 4;
    const int d2 = tq & 15;
    const int ch = h * 32 + d2 * 2;
    const __half* vb = g_vh + (size_t)b * NV * EMBED + ch;
    float2 acc = make_float2(0.f, 0.f);
#pragma unroll
    for (int i = 0; i < 16; i++) {
        const int s = h * 16 + i;
#pragma unroll
        for (int cc = 0; cc < 4; cc++) {
            const float w = s_wt[qi][s][cc];
            const __half2 hv = *reinterpret_cast<const __half2*>(vb + (size_t)s_pos[qi][s][cc] * EMBED);
            const float2 f = __half22float2(hv);
            acc.x = fmaf(w, f.x, acc.x);
            acc.y = fmaf(w, f.y, acc.y);
        }
    }
    *reinterpret_cast<float2*>(&g_attn[(size_t)q * EMBED + ch]) = acc;
}

// ---------------- launch ----------------
extern "C" void kernel_launch(void* const* d_in, const int* in_sizes, int n_in,
                              void* d_out, int out_size)
{
    const float* query  = (const float*)d_in[0];
    const float* value  = (const float*)d_in[1];
    const float* rp     = (const float*)d_in[2];
    const float* W_off  = (const float*)d_in[4];
    const float* b_off  = (const float*)d_in[5];
    const float* W_attn = (const float*)d_in[6];
    const float* b_attn = (const float*)d_in[7];
    const float* W_v    = (const float*)d_in[8];
    const float* b_v    = (const float*)d_in[9];
    const float* W_out  = (const float*)d_in[10];
    const float* b_out  = (const float*)d_in[11];
    float* out = (float*)d_out;

    float *poff, *paw, *pattn;
    __half* pvh;
    cudaGetSymbolAddress((void**)&pvh,   g_vh);
    cudaGetSymbolAddress((void**)&poff,  g_off);
    cudaGetSymbolAddress((void**)&paw,   g_aw);
    cudaGetSymbolAddress((void**)&pattn, g_attn);

    __nv_bfloat16 *bvh, *bvl, *boh, *bol, *bah, *bal, *buh, *bul;
    cudaGetSymbolAddress((void**)&bvh, g_Bvh); cudaGetSymbolAddress((void**)&bvl, g_Bvl);
    cudaGetSymbolAddress((void**)&boh, g_Boh); cudaGetSymbolAddress((void**)&bol, g_Bol);
    cudaGetSymbolAddress((void**)&bah, g_Bah); cudaGetSymbolAddress((void**)&bal, g_Bal);
    cudaGetSymbolAddress((void**)&buh, g_Buh); cudaGetSymbolAddress((void**)&bul, g_Bul);

    cudaFuncSetAttribute(mma_gemm_kernel,
                         cudaFuncAttributeMaxDynamicSharedMemorySize, DSMEM_BYTES);

    conv_all_kernel<<<896, 256>>>(W_v, W_off, W_attn, W_out,
                                  bvh, bvl, boh, bol, bah, bal, buh, bul);

    const int Mv = BS * NV;
    {   // value projection -> fp16
        dim3 grid(4, (Mv + 127) / 128);
        mma_gemm_kernel<<<grid, 256, DSMEM_BYTES>>>(value, bvh, bvl, b_v, nullptr,
                                                    nullptr, pvh, Mv, 256);
    }
    {   // sampling offsets
        dim3 grid(4, (NBQ + 127) / 128);
        mma_gemm_kernel<<<grid, 256, DSMEM_BYTES>>>(query, boh, bol, b_off, nullptr,
                                                    poff, nullptr, NBQ, 256);
    }
    {   // attention logits
        dim3 grid(2, (NBQ + 127) / 128);
        mma_gemm_kernel<<<grid, 256, DSMEM_BYTES>>>(query, bah, bal, b_attn, nullptr,
                                                    paw, nullptr, NBQ, 128);
    }
    msda_sample_kernel<<<NBQ / 2, 256>>>(rp);
    {   // output projection + residual
        dim3 grid(4, (NBQ + 127) / 128);
        mma_gemm_kernel<<<grid, 256, DSMEM_BYTES>>>(pattn, buh, bul, b_out, query,
                                                    out, nullptr, NBQ, 256);
    }
}

// round 8
// speedup vs baseline: 2.4380x; 1.0371x over previous
#include <cuda_runtime.h>
#include <cuda_bf16.h>
#include <cuda_fp16.h>
#include <cstdint>

// ---------------- problem constants ----------------
#define BS      8
#define NQ      900
#define EMBED   256
#define HEADS   8
#define LEVELS  4
#define POINTS  4
#define NV      13294
#define NBQ     (BS * NQ)      // 7200
#define KDIM    256

__device__ __constant__ int c_LH[4] = {100, 50, 25, 13};
__device__ __constant__ int c_LW[4] = {100, 50, 25, 13};
__device__ __constant__ int c_LS[4] = {0, 10000, 12500, 13125};

// ---------------- scratch ----------------
__device__ __half g_vh[(size_t)BS * NV * EMBED];
__device__ float g_qa[(size_t)NBQ * 384];          // fused: offsets[0:256) + logits[256:384)
__device__ float g_attn[(size_t)NBQ * EMBED];
__device__ float g_bias_qa[384];

__device__ __nv_bfloat16 g_Bvh[256 * 256], g_Bvl[256 * 256];
__device__ __nv_bfloat16 g_Bqh[384 * 256], g_Bql[384 * 256];   // fused off+attn weights
__device__ __nv_bfloat16 g_Buh[256 * 256], g_Bul[256 * 256];

// ---------------- helpers ----------------
__device__ __forceinline__ uint32_t smem_u32(const void* p) {
    uint32_t a;
    asm("{ .reg .u64 t; cvta.to.shared.u64 t, %1; cvt.u32.u64 %0, t; }" : "=r"(a) : "l"(p));
    return a;
}
__device__ __forceinline__ uint32_t pack_bf16(float x, float y) {
    __nv_bfloat162 h = __floats2bfloat162_rn(x, y);
    return *reinterpret_cast<uint32_t*>(&h);
}
__device__ __forceinline__ void mma_bf16(float d[4],
                                         uint32_t a0, uint32_t a1, uint32_t a2, uint32_t a3,
                                         uint32_t b0, uint32_t b1) {
    asm volatile(
        "mma.sync.aligned.m16n8k16.row.col.f32.bf16.bf16.f32 "
        "{%0,%1,%2,%3}, {%4,%5,%6,%7}, {%8,%9}, {%0,%1,%2,%3};"
        : "+f"(d[0]), "+f"(d[1]), "+f"(d[2]), "+f"(d[3])
        : "r"(a0), "r"(a1), "r"(a2), "r"(a3), "r"(b0), "r"(b1));
}
__device__ __forceinline__ void ldsm_x4(uint32_t& r0, uint32_t& r1, uint32_t& r2, uint32_t& r3,
                                        uint32_t addr) {
    asm volatile("ldmatrix.sync.aligned.m8n8.x4.shared.b16 {%0,%1,%2,%3}, [%4];"
                 : "=r"(r0), "=r"(r1), "=r"(r2), "=r"(r3) : "r"(addr));
}
__device__ __forceinline__ void cp_async16(uint32_t saddr, const void* gaddr) {
    asm volatile("cp.async.ca.shared.global [%0], [%1], 16;" :: "r"(saddr), "l"(gaddr));
}

// ---------------- fused weight conversion + bias pack ----------------
__global__ void conv_all_kernel(const float* __restrict__ Wv,
                                const float* __restrict__ Woff,
                                const float* __restrict__ Wattn,
                                const float* __restrict__ Wout,
                                const float* __restrict__ b_off,
                                const float* __restrict__ b_attn)
{
    int i = blockIdx.x * 256 + threadIdx.x;
    const float* W; __nv_bfloat16 *Bh, *Bl; int N, j, nbase;
    if (i < 65536)        { W = Wv;    Bh = g_Bvh; Bl = g_Bvl; N = 256; j = i;          nbase = 0; }
    else if (i < 131072)  { W = Woff;  Bh = g_Bqh; Bl = g_Bql; N = 256; j = i - 65536;  nbase = 0; }
    else if (i < 163840)  { W = Wattn; Bh = g_Bqh; Bl = g_Bql; N = 128; j = i - 131072; nbase = 256; }
    else if (i < 229376)  { W = Wout;  Bh = g_Buh; Bl = g_Bul; N = 256; j = i - 163840; nbase = 0; }
    else if (i < 229760)  {
        int j2 = i - 229376;
        g_bias_qa[j2] = (j2 < 256) ? b_off[j2] : b_attn[j2 - 256];
        return;
    } else return;
    int k = j / N, n = j % N;
    float x = W[j];
    __nv_bfloat16 hb = __float2bfloat16(x);
    float lo = x - __bfloat162float(hb);
    Bh[(size_t)(nbase + n) * KDIM + k] = hb;
    Bl[(size_t)(nbase + n) * KDIM + k] = __float2bfloat16(lo);
}

// ---------------- HMMA GEMM: CTA 128x64, warp 32x32, ldmatrix + cp.async ----
#define KC 32
#define ROWB 80
#define A_HI_B 0
#define A_LO_B (128 * ROWB)
#define B_HI_B (2 * 128 * ROWB)
#define B_LO_B (B_HI_B + 64 * ROWB)
#define STAGE_B (B_LO_B + 64 * ROWB)
#define DSMEM_BYTES (2 * STAGE_B)

__global__ __launch_bounds__(256, 2)
void mma_gemm_kernel(const float* __restrict__ A,
                     const __nv_bfloat16* __restrict__ Bh,
                     const __nv_bfloat16* __restrict__ Bl,
                     const float* __restrict__ bias,
                     const float* __restrict__ resid,
                     float* __restrict__ C,
                     __half* __restrict__ Ch,
                     int M, int Ntot)
{
    extern __shared__ char smemc[];
    __shared__ float s_bias[64];

    const int tid = threadIdx.x;
    const int wid = tid >> 5;
    const int lane = tid & 31;
    const int g = lane >> 2;
    const int tig = lane & 3;
    const int wm = wid & 3;
    const int wn = wid >> 2;
    const int m0 = blockIdx.y * 128;
    const int n0 = blockIdx.x * 64;

    if (tid < 64) s_bias[tid] = bias[n0 + tid];

    const uint32_t sbase = smem_u32(smemc);

    float acc[2][4][4];
#pragma unroll
    for (int mt = 0; mt < 2; mt++)
#pragma unroll
        for (int nt = 0; nt < 4; nt++)
#pragma unroll
            for (int q = 0; q < 4; q++) acc[mt][nt][q] = 0.f;

    const int a_row[4] = { (tid + 0) >> 3, (tid + 256) >> 3, (tid + 512) >> 3, (tid + 768) >> 3 };
    const int a_q = tid & 7;
    const int b_row0 = tid >> 2, b_c0 = tid & 3;

    const int lm_arow = lane & 15;
    const int lm_akoff = (lane >> 4) * 16;
    const int lm_brow = (lane & 7) + ((lane >> 4) << 3);
    const int lm_bkoff = ((lane >> 3) & 1) * 16;

    auto fill_A = [&](int stage, const float4* pa) {
#pragma unroll
        for (int i = 0; i < 4; i++) {
            const float4 f = pa[i];
            float hx = __bfloat162float(__float2bfloat16(f.x));
            float hy = __bfloat162float(__float2bfloat16(f.y));
            float hz = __bfloat162float(__float2bfloat16(f.z));
            float hw = __bfloat162float(__float2bfloat16(f.w));
            const uint32_t off = (uint32_t)(a_row[i] * ROWB + a_q * 8);
            *reinterpret_cast<uint2*>(smemc + stage * STAGE_B + A_HI_B + off) =
                make_uint2(pack_bf16(f.x, f.y), pack_bf16(f.z, f.w));
            *reinterpret_cast<uint2*>(smemc + stage * STAGE_B + A_LO_B + off) =
                make_uint2(pack_bf16(f.x - hx, f.y - hy), pack_bf16(f.z - hz, f.w - hw));
        }
    };

    auto issue_B = [&](int stage, int k0) {
        const uint32_t Sb = sbase + stage * STAGE_B;
        cp_async16(Sb + B_HI_B + b_row0 * ROWB + b_c0 * 16,
                   Bh + (size_t)(n0 + b_row0) * KDIM + k0 + b_c0 * 8);
        cp_async16(Sb + B_LO_B + b_row0 * ROWB + b_c0 * 16,
                   Bl + (size_t)(n0 + b_row0) * KDIM + k0 + b_c0 * 8);
        asm volatile("cp.async.commit_group;" ::: "memory");
    };

    {
        issue_B(0, 0);
        float4 pa[4];
#pragma unroll
        for (int i = 0; i < 4; i++) {
            pa[i] = make_float4(0.f, 0.f, 0.f, 0.f);
            if (m0 + a_row[i] < M)
                pa[i] = *reinterpret_cast<const float4*>(&A[(size_t)(m0 + a_row[i]) * KDIM + a_q * 4]);
        }
        fill_A(0, pa);
        asm volatile("cp.async.wait_group 0;" ::: "memory");
    }
    __syncthreads();

    const int ntiles = KDIM / KC;
    int buf = 0;

    for (int kt = 0; kt < ntiles; kt++) {
        const bool more = (kt + 1 < ntiles);
        float4 pa[4];
        if (more) {
            const int k0 = (kt + 1) * KC;
            issue_B(buf ^ 1, k0);
#pragma unroll
            for (int i = 0; i < 4; i++) {
                pa[i] = make_float4(0.f, 0.f, 0.f, 0.f);
                if (m0 + a_row[i] < M)
                    pa[i] = *reinterpret_cast<const float4*>(&A[(size_t)(m0 + a_row[i]) * KDIM + k0 + a_q * 4]);
            }
        }

        const uint32_t Sb = sbase + buf * STAGE_B;
#pragma unroll
        for (int kk = 0; kk < 2; kk++) {
            uint32_t bh[4][2], bl[4][2];
#pragma unroll
            for (int p = 0; p < 2; p++) {
                const uint32_t baddr = Sb + (uint32_t)((wn * 32 + p * 16 + lm_brow) * ROWB + kk * 32 + lm_bkoff);
                ldsm_x4(bh[2 * p][0], bh[2 * p][1], bh[2 * p + 1][0], bh[2 * p + 1][1],
                        baddr + B_HI_B);
                ldsm_x4(bl[2 * p][0], bl[2 * p][1], bl[2 * p + 1][0], bl[2 * p + 1][1],
                        baddr + B_LO_B);
            }
            uint32_t ah[2][4], al[2][4];
#pragma unroll
            for (int mt = 0; mt < 2; mt++) {
                const uint32_t aaddr = Sb + (uint32_t)((wm * 32 + mt * 16 + lm_arow) * ROWB + kk * 32 + lm_akoff);
                ldsm_x4(ah[mt][0], ah[mt][1], ah[mt][2], ah[mt][3], aaddr + A_HI_B);
                ldsm_x4(al[mt][0], al[mt][1], al[mt][2], al[mt][3], aaddr + A_LO_B);
            }
#pragma unroll
            for (int mt = 0; mt < 2; mt++)
#pragma unroll
                for (int nt = 0; nt < 4; nt++) {
                    mma_bf16(acc[mt][nt], ah[mt][0], ah[mt][1], ah[mt][2], ah[mt][3],
                             bh[nt][0], bh[nt][1]);
                    mma_bf16(acc[mt][nt], ah[mt][0], ah[mt][1], ah[mt][2], ah[mt][3],
                             bl[nt][0], bl[nt][1]);
                    mma_bf16(acc[mt][nt], al[mt][0], al[mt][1], al[mt][2], al[mt][3],
                             bh[nt][0], bh[nt][1]);
                }
        }

        if (more) {
            fill_A(buf ^ 1, pa);
            asm volatile("cp.async.wait_group 0;" ::: "memory");
            __syncthreads();
            buf ^= 1;
        }
    }

    // ---- epilogue ----
#pragma unroll
    for (int mt = 0; mt < 2; mt++) {
        const int r0 = m0 + wm * 32 + mt * 16 + g;
        const int r1 = r0 + 8;
#pragma unroll
        for (int nt = 0; nt < 4; nt++) {
            const int cloc = wn * 32 + nt * 8 + tig * 2;
            const int col = n0 + cloc;
            const float b0 = s_bias[cloc], b1 = s_bias[cloc + 1];
            float2 v0 = make_float2(acc[mt][nt][0] + b0, acc[mt][nt][1] + b1);
            float2 v1 = make_float2(acc[mt][nt][2] + b0, acc[mt][nt][3] + b1);
            if (resid) {
                if (r0 < M) {
                    const float2 rv = *reinterpret_cast<const float2*>(&resid[(size_t)r0 * 256 + col]);
                    v0.x += rv.x; v0.y += rv.y;
                }
                if (r1 < M) {
                    const float2 rv = *reinterpret_cast<const float2*>(&resid[(size_t)r1 * 256 + col]);
                    v1.x += rv.x; v1.y += rv.y;
                }
            }
            if (Ch) {
                if (r0 < M)
                    *reinterpret_cast<__half2*>(&Ch[(size_t)r0 * Ntot + col]) = __floats2half2_rn(v0.x, v0.y);
                if (r1 < M)
                    *reinterpret_cast<__half2*>(&Ch[(size_t)r1 * Ntot + col]) = __floats2half2_rn(v1.x, v1.y);
            } else {
                if (r0 < M) *reinterpret_cast<float2*>(&C[(size_t)r0 * Ntot + col]) = v0;
                if (r1 < M) *reinterpret_cast<float2*>(&C[(size_t)r1 * Ntot + col]) = v1;
            }
        }
    }
}

// ---------------- sampling kernel: 2 queries/block, half2 gathers ----------
__global__ __launch_bounds__(256)
void msda_sample_kernel(const float* __restrict__ rp)
{
    const int tid = threadIdx.x;
    const int qi = tid >> 7;
    const int tq = tid & 127;
    const int q = blockIdx.x * 2 + qi;
    const int b = q / NQ;

    __shared__ float s_aw[2][128];
    __shared__ int   s_pos[2][128][4];
    __shared__ float s_wt[2][128][4];

    s_aw[qi][tq] = g_qa[(size_t)q * 384 + 256 + tq];
    __syncthreads();

    if (tid < 16) {
        const int sq = tid >> 3, h = tid & 7;
        float* aw = &s_aw[sq][h * 16];
        float mx = -1e30f;
#pragma unroll
        for (int i = 0; i < 16; i++) mx = fmaxf(mx, aw[i]);
        float e[16];
        float sum = 0.f;
#pragma unroll
        for (int i = 0; i < 16; i++) { e[i] = __expf(aw[i] - mx); sum += e[i]; }
        float inv = 1.f / sum;
#pragma unroll
        for (int i = 0; i < 16; i++) aw[i] = e[i] * inv;
    }
    __syncthreads();

    {
        const int s = tq;
        const int l = (s >> 2) & 3;
        const float aw = s_aw[qi][s];
        const float offx = g_qa[(size_t)q * 384 + s * 2];
        const float offy = g_qa[(size_t)q * 384 + s * 2 + 1];
        const float rx = rp[((size_t)q * LEVELS + l) * 2];
        const float ry = rp[((size_t)q * LEVELS + l) * 2 + 1];
        const int W = c_LW[l], H = c_LH[l], st = c_LS[l];

        const float locx = rx + offx / (float)W;
        const float locy = ry + offy / (float)H;
        const float x = locx * (float)W - 0.5f;
        const float y = locy * (float)H - 0.5f;
        const float x0f = floorf(x), y0f = floorf(y);
        const float lx = x - x0f, ly = y - y0f;
        const int x0 = (int)x0f, y0 = (int)y0f;

#pragma unroll
        for (int cc = 0; cc < 4; cc++) {
            const int dx = cc & 1, dy = cc >> 1;
            const int xi = x0 + dx, yi = y0 + dy;
            const float wx = dx ? lx : (1.f - lx);
            const float wy = dy ? ly : (1.f - ly);
            const bool valid = (xi >= 0) && (xi < W) && (yi >= 0) && (yi < H);
            const int xc = min(max(xi, 0), W - 1);
            const int yc = min(max(yi, 0), H - 1);
            s_pos[qi][s][cc] = st + yc * W + xc;
            s_wt[qi][s][cc] = valid ? (wx * wy * aw) : 0.f;
        }
    }
    __syncthreads();

    const int h = tq >> 4;
    const int d2 = tq & 15;
    const int ch = h * 32 + d2 * 2;
    const __half* vb = g_vh + (size_t)b * NV * EMBED + ch;
    float2 acc = make_float2(0.f, 0.f);
#pragma unroll
    for (int i = 0; i < 16; i++) {
        const int s = h * 16 + i;
#pragma unroll
        for (int cc = 0; cc < 4; cc++) {
            const float w = s_wt[qi][s][cc];
            const __half2 hv = *reinterpret_cast<const __half2*>(vb + (size_t)s_pos[qi][s][cc] * EMBED);
            const float2 f = __half22float2(hv);
            acc.x = fmaf(w, f.x, acc.x);
            acc.y = fmaf(w, f.y, acc.y);
        }
    }
    *reinterpret_cast<float2*>(&g_attn[(size_t)q * EMBED + ch]) = acc;
}

// ---------------- launch ----------------
extern "C" void kernel_launch(void* const* d_in, const int* in_sizes, int n_in,
                              void* d_out, int out_size)
{
    const float* query  = (const float*)d_in[0];
    const float* value  = (const float*)d_in[1];
    const float* rp     = (const float*)d_in[2];
    const float* W_off  = (const float*)d_in[4];
    const float* b_off  = (const float*)d_in[5];
    const float* W_attn = (const float*)d_in[6];
    const float* b_attn = (const float*)d_in[7];
    const float* W_v    = (const float*)d_in[8];
    const float* b_v    = (const float*)d_in[9];
    const float* W_out  = (const float*)d_in[10];
    const float* b_out  = (const float*)d_in[11];
    float* out = (float*)d_out;

    float *pqa, *pattn, *pbias_qa;
    __half* pvh;
    cudaGetSymbolAddress((void**)&pvh,     g_vh);
    cudaGetSymbolAddress((void**)&pqa,     g_qa);
    cudaGetSymbolAddress((void**)&pattn,   g_attn);
    cudaGetSymbolAddress((void**)&pbias_qa, g_bias_qa);

    __nv_bfloat16 *bvh, *bvl, *bqh, *bql, *buh, *bul;
    cudaGetSymbolAddress((void**)&bvh, g_Bvh); cudaGetSymbolAddress((void**)&bvl, g_Bvl);
    cudaGetSymbolAddress((void**)&bqh, g_Bqh); cudaGetSymbolAddress((void**)&bql, g_Bql);
    cudaGetSymbolAddress((void**)&buh, g_Buh); cudaGetSymbolAddress((void**)&bul, g_Bul);

    cudaFuncSetAttribute(mma_gemm_kernel,
                         cudaFuncAttributeMaxDynamicSharedMemorySize, DSMEM_BYTES);

    // side stream + fork/join events (created once; host objects only)
    static cudaStream_t s2 = nullptr;
    static cudaEvent_t evFork = nullptr, evJoin = nullptr;
    if (!s2) {
        cudaStreamCreateWithFlags(&s2, cudaStreamNonBlocking);
        cudaEventCreateWithFlags(&evFork, cudaEventDisableTiming);
        cudaEventCreateWithFlags(&evJoin, cudaEventDisableTiming);
    }

    // conv on main stream
    conv_all_kernel<<<898, 256>>>(W_v, W_off, W_attn, W_out, b_off, b_attn);

    // fork: query-side fused GEMM on s2, value GEMM on main
    cudaEventRecord(evFork, 0);
    cudaStreamWaitEvent(s2, evFork, 0);

    {   // fused offsets+logits: (NBQ,256)@(256,384), grid (6,57)
        dim3 grid(6, (NBQ + 127) / 128);
        mma_gemm_kernel<<<grid, 256, DSMEM_BYTES, s2>>>(query, bqh, bql, pbias_qa, nullptr,
                                                        pqa, nullptr, NBQ, 384);
    }

    const int Mv = BS * NV;
    {   // value projection -> fp16 (main stream, overlaps with s2)
        dim3 grid(4, (Mv + 127) / 128);
        mma_gemm_kernel<<<grid, 256, DSMEM_BYTES>>>(value, bvh, bvl, b_v, nullptr,
                                                    nullptr, pvh, Mv, 256);
    }

    // join
    cudaEventRecord(evJoin, s2);
    cudaStreamWaitEvent(0, evJoin, 0);

    msda_sample_kernel<<<NBQ / 2, 256>>>(rp);

    {   // output projection + residual
        dim3 grid(4, (NBQ + 127) / 128);
        mma_gemm_kernel<<<grid, 256, DSMEM_BYTES>>>(pattn, buh, bul, b_out, query,
                                                    out, nullptr, NBQ, 256);
    }
}

// round 9
// speedup vs baseline: 2.9128x; 1.1947x over previous
#include <cuda_runtime.h>
#include <cuda_bf16.h>
#include <cuda_fp16.h>
#include <cstdint>

// ---------------- problem constants ----------------
#define BS      8
#define NQ      900
#define EMBED   256
#define HEADS   8
#define LEVELS  4
#define POINTS  4
#define NV      13294
#define NBQ     (BS * NQ)      // 7200
#define KDIM    256

__device__ __constant__ int c_LH[4] = {100, 50, 25, 13};
__device__ __constant__ int c_LW[4] = {100, 50, 25, 13};
__device__ __constant__ int c_LS[4] = {0, 10000, 12500, 13125};

// ---------------- scratch ----------------
__device__ __half g_vh[(size_t)BS * NV * EMBED];
__device__ float g_qa[(size_t)NBQ * 384];          // fused: offsets[0:256) + logits[256:384)
__device__ float g_attn[(size_t)NBQ * EMBED];
__device__ float g_bias_qa[384];

// weights as MMA "B": [N, K] row-major, fp16 hi/lo (hi + residual)
__device__ __half g_Bvh[256 * 256], g_Bvl[256 * 256];
__device__ __half g_Bqh[384 * 256], g_Bql[384 * 256];
__device__ __half g_Buh[256 * 256], g_Bul[256 * 256];

// ---------------- helpers ----------------
__device__ __forceinline__ uint32_t smem_u32(const void* p) {
    uint32_t a;
    asm("{ .reg .u64 t; cvta.to.shared.u64 t, %1; cvt.u32.u64 %0, t; }" : "=r"(a) : "l"(p));
    return a;
}
__device__ __forceinline__ uint32_t pack_h2(float x, float y) {
    __half2 h = __floats2half2_rn(x, y);
    return *reinterpret_cast<uint32_t*>(&h);
}
__device__ __forceinline__ void mma_f16(float d[4],
                                        uint32_t a0, uint32_t a1, uint32_t a2, uint32_t a3,
                                        uint32_t b0, uint32_t b1) {
    asm volatile(
        "mma.sync.aligned.m16n8k16.row.col.f32.f16.f16.f32 "
        "{%0,%1,%2,%3}, {%4,%5,%6,%7}, {%8,%9}, {%0,%1,%2,%3};"
        : "+f"(d[0]), "+f"(d[1]), "+f"(d[2]), "+f"(d[3])
        : "r"(a0), "r"(a1), "r"(a2), "r"(a3), "r"(b0), "r"(b1));
}
__device__ __forceinline__ void ldsm_x4(uint32_t& r0, uint32_t& r1, uint32_t& r2, uint32_t& r3,
                                        uint32_t addr) {
    asm volatile("ldmatrix.sync.aligned.m8n8.x4.shared.b16 {%0,%1,%2,%3}, [%4];"
                 : "=r"(r0), "=r"(r1), "=r"(r2), "=r"(r3) : "r"(addr));
}
__device__ __forceinline__ void ldsm_x2(uint32_t& r0, uint32_t& r1, uint32_t addr) {
    asm volatile("ldmatrix.sync.aligned.m8n8.x2.shared.b16 {%0,%1}, [%2];"
                 : "=r"(r0), "=r"(r1) : "r"(addr));
}
__device__ __forceinline__ void cp_async16(uint32_t saddr, const void* gaddr) {
    asm volatile("cp.async.ca.shared.global [%0], [%1], 16;" :: "r"(saddr), "l"(gaddr));
}

// ---------------- fused weight conversion + bias pack ----------------
__global__ void conv_all_kernel(const float* __restrict__ Wv,
                                const float* __restrict__ Woff,
                                const float* __restrict__ Wattn,
                                const float* __restrict__ Wout,
                                const float* __restrict__ b_off,
                                const float* __restrict__ b_attn)
{
    int i = blockIdx.x * 256 + threadIdx.x;
    const float* W; __half *Bh, *Bl; int N, j, nbase;
    if (i < 65536)        { W = Wv;    Bh = g_Bvh; Bl = g_Bvl; N = 256; j = i;          nbase = 0; }
    else if (i < 131072)  { W = Woff;  Bh = g_Bqh; Bl = g_Bql; N = 256; j = i - 65536;  nbase = 0; }
    else if (i < 163840)  { W = Wattn; Bh = g_Bqh; Bl = g_Bql; N = 128; j = i - 131072; nbase = 256; }
    else if (i < 229376)  { W = Wout;  Bh = g_Buh; Bl = g_Bul; N = 256; j = i - 163840; nbase = 0; }
    else if (i < 229760)  {
        int j2 = i - 229376;
        g_bias_qa[j2] = (j2 < 256) ? b_off[j2] : b_attn[j2 - 256];
        return;
    } else return;
    int k = j / N, n = j % N;
    float x = W[j];
    __half hb = __float2half_rn(x);
    float lo = x - __half2float(hb);
    Bh[(size_t)(nbase + n) * KDIM + k] = hb;
    Bl[(size_t)(nbase + n) * KDIM + k] = __float2half_rn(lo);
}

// ---------------- HMMA GEMM: CTA 128x64, warp 32x32, fp16 2-term split ------
// C[M,Ntot] = A[M,256] @ B[N,256]^T + bias (+resid).  KC=32, double-buffered.
#define KC 32
#define ROWB 80                          // 32 fp16 = 64 B + 16 pad
#define A_B 0
#define B_HI_B (128 * ROWB)              // 10240
#define B_LO_B (B_HI_B + 64 * ROWB)      // 15360
#define STAGE_B (B_LO_B + 64 * ROWB)     // 20480
#define DSMEM_BYTES (2 * STAGE_B)        // 40960

__global__ __launch_bounds__(256, 2)
void mma_gemm_kernel(const float* __restrict__ A,
                     const __half* __restrict__ Bh,
                     const __half* __restrict__ Bl,
                     const float* __restrict__ bias,
                     const float* __restrict__ resid,
                     float* __restrict__ C,
                     __half* __restrict__ Ch,
                     int M, int Ntot)
{
    extern __shared__ char smemc[];
    __shared__ float s_bias[64];

    const int tid = threadIdx.x;
    const int wid = tid >> 5;
    const int lane = tid & 31;
    const int g = lane >> 2;
    const int tig = lane & 3;
    const int wm = wid & 3;
    const int wn = wid >> 2;
    const int m0 = blockIdx.y * 128;
    const int n0 = blockIdx.x * 64;

    if (tid < 64) s_bias[tid] = bias[n0 + tid];

    const uint32_t sbase = smem_u32(smemc);

    float acc[2][4][4];
#pragma unroll
    for (int mt = 0; mt < 2; mt++)
#pragma unroll
        for (int nt = 0; nt < 4; nt++)
#pragma unroll
            for (int q = 0; q < 4; q++) acc[mt][nt][q] = 0.f;

    const int a_row[4] = { (tid + 0) >> 3, (tid + 256) >> 3, (tid + 512) >> 3, (tid + 768) >> 3 };
    const int a_q = tid & 7;
    const int b_row0 = tid >> 2, b_c0 = tid & 3;

    const int lm_arow = lane & 15;
    const int lm_akoff = (lane >> 4) * 16;
    const int lm_brow = (lane & 7) + ((lane >> 4) << 3);
    const int lm_bkoff = ((lane >> 3) & 1) * 16;

    auto fill_A = [&](int stage, const float4* pa) {
#pragma unroll
        for (int i = 0; i < 4; i++) {
            const float4 f = pa[i];
            const uint32_t off = (uint32_t)(a_row[i] * ROWB + a_q * 8);
            *reinterpret_cast<uint2*>(smemc + stage * STAGE_B + A_B + off) =
                make_uint2(pack_h2(f.x, f.y), pack_h2(f.z, f.w));
        }
    };

    auto issue_B = [&](int stage, int k0) {
        const uint32_t Sb = sbase + stage * STAGE_B;
        cp_async16(Sb + B_HI_B + b_row0 * ROWB + b_c0 * 16,
                   Bh + (size_t)(n0 + b_row0) * KDIM + k0 + b_c0 * 8);
        cp_async16(Sb + B_LO_B + b_row0 * ROWB + b_c0 * 16,
                   Bl + (size_t)(n0 + b_row0) * KDIM + k0 + b_c0 * 8);
        asm volatile("cp.async.commit_group;" ::: "memory");
    };

    {
        issue_B(0, 0);
        float4 pa[4];
#pragma unroll
        for (int i = 0; i < 4; i++) {
            pa[i] = make_float4(0.f, 0.f, 0.f, 0.f);
            if (m0 + a_row[i] < M)
                pa[i] = *reinterpret_cast<const float4*>(&A[(size_t)(m0 + a_row[i]) * KDIM + a_q * 4]);
        }
        fill_A(0, pa);
        asm volatile("cp.async.wait_group 0;" ::: "memory");
    }
    __syncthreads();

    const int ntiles = KDIM / KC;
    int buf = 0;

    for (int kt = 0; kt < ntiles; kt++) {
        const bool more = (kt + 1 < ntiles);
        float4 pa[4];
        if (more) {
            const int k0 = (kt + 1) * KC;
            issue_B(buf ^ 1, k0);
#pragma unroll
            for (int i = 0; i < 4; i++) {
                pa[i] = make_float4(0.f, 0.f, 0.f, 0.f);
                if (m0 + a_row[i] < M)
                    pa[i] = *reinterpret_cast<const float4*>(&A[(size_t)(m0 + a_row[i]) * KDIM + k0 + a_q * 4]);
            }
        }

        const uint32_t Sb = sbase + buf * STAGE_B;
#pragma unroll
        for (int kk = 0; kk < 2; kk++) {
            uint32_t bh[4][2], bl[4][2];
#pragma unroll
            for (int p = 0; p < 2; p++) {
                const uint32_t baddr = Sb + (uint32_t)((wn * 32 + p * 16 + lm_brow) * ROWB + kk * 32 + lm_bkoff);
                ldsm_x4(bh[2 * p][0], bh[2 * p][1], bh[2 * p + 1][0], bh[2 * p + 1][1],
                        baddr + B_HI_B);
                ldsm_x4(bl[2 * p][0], bl[2 * p][1], bl[2 * p + 1][0], bl[2 * p + 1][1],
                        baddr + B_LO_B);
            }
            uint32_t ah[2][4];
#pragma unroll
            for (int mt = 0; mt < 2; mt++) {
                const uint32_t aaddr = Sb + (uint32_t)((wm * 32 + mt * 16 + lm_arow) * ROWB + kk * 32 + lm_akoff);
                ldsm_x4(ah[mt][0], ah[mt][1], ah[mt][2], ah[mt][3], aaddr + A_B);
            }
#pragma unroll
            for (int mt = 0; mt < 2; mt++)
#pragma unroll
                for (int nt = 0; nt < 4; nt++) {
                    mma_f16(acc[mt][nt], ah[mt][0], ah[mt][1], ah[mt][2], ah[mt][3],
                            bh[nt][0], bh[nt][1]);
                    mma_f16(acc[mt][nt], ah[mt][0], ah[mt][1], ah[mt][2], ah[mt][3],
                            bl[nt][0], bl[nt][1]);
                }
        }

        if (more) {
            fill_A(buf ^ 1, pa);
            asm volatile("cp.async.wait_group 0;" ::: "memory");
            __syncthreads();
            buf ^= 1;
        }
    }

    // ---- epilogue ----
#pragma unroll
    for (int mt = 0; mt < 2; mt++) {
        const int r0 = m0 + wm * 32 + mt * 16 + g;
        const int r1 = r0 + 8;
#pragma unroll
        for (int nt = 0; nt < 4; nt++) {
            const int cloc = wn * 32 + nt * 8 + tig * 2;
            const int col = n0 + cloc;
            const float b0 = s_bias[cloc], b1 = s_bias[cloc + 1];
            float2 v0 = make_float2(acc[mt][nt][0] + b0, acc[mt][nt][1] + b1);
            float2 v1 = make_float2(acc[mt][nt][2] + b0, acc[mt][nt][3] + b1);
            if (resid) {
                if (r0 < M) {
                    const float2 rv = *reinterpret_cast<const float2*>(&resid[(size_t)r0 * 256 + col]);
                    v0.x += rv.x; v0.y += rv.y;
                }
                if (r1 < M) {
                    const float2 rv = *reinterpret_cast<const float2*>(&resid[(size_t)r1 * 256 + col]);
                    v1.x += rv.x; v1.y += rv.y;
                }
            }
            if (Ch) {
                if (r0 < M)
                    *reinterpret_cast<__half2*>(&Ch[(size_t)r0 * Ntot + col]) = __floats2half2_rn(v0.x, v0.y);
                if (r1 < M)
                    *reinterpret_cast<__half2*>(&Ch[(size_t)r1 * Ntot + col]) = __floats2half2_rn(v1.x, v1.y);
            } else {
                if (r0 < M) *reinterpret_cast<float2*>(&C[(size_t)r0 * Ntot + col]) = v0;
                if (r1 < M) *reinterpret_cast<float2*>(&C[(size_t)r1 * Ntot + col]) = v1;
            }
        }
    }
}

// ---------------- sampling kernel: 2 queries/block, half2 gathers ----------
__global__ __launch_bounds__(256)
void msda_sample_kernel(const float* __restrict__ rp)
{
    const int tid = threadIdx.x;
    const int qi = tid >> 7;
    const int tq = tid & 127;
    const int q = blockIdx.x * 2 + qi;
    const int b = q / NQ;

    __shared__ float s_aw[2][128];
    __shared__ int   s_pos[2][128][4];
    __shared__ float s_wt[2][128][4];

    s_aw[qi][tq] = g_qa[(size_t)q * 384 + 256 + tq];
    __syncthreads();

    if (tid < 16) {
        const int sq = tid >> 3, h = tid & 7;
        float* aw = &s_aw[sq][h * 16];
        float mx = -1e30f;
#pragma unroll
        for (int i = 0; i < 16; i++) mx = fmaxf(mx, aw[i]);
        float e[16];
        float sum = 0.f;
#pragma unroll
        for (int i = 0; i < 16; i++) { e[i] = __expf(aw[i] - mx); sum += e[i]; }
        float inv = 1.f / sum;
#pragma unroll
        for (int i = 0; i < 16; i++) aw[i] = e[i] * inv;
    }
    __syncthreads();

    {
        const int s = tq;
        const int l = (s >> 2) & 3;
        const float aw = s_aw[qi][s];
        const float offx = g_qa[(size_t)q * 384 + s * 2];
        const float offy = g_qa[(size_t)q * 384 + s * 2 + 1];
        const float rx = rp[((size_t)q * LEVELS + l) * 2];
        const float ry = rp[((size_t)q * LEVELS + l) * 2 + 1];
        const int W = c_LW[l], H = c_LH[l], st = c_LS[l];

        const float locx = rx + offx / (float)W;
        const float locy = ry + offy / (float)H;
        const float x = locx * (float)W - 0.5f;
        const float y = locy * (float)H - 0.5f;
        const float x0f = floorf(x), y0f = floorf(y);
        const float lx = x - x0f, ly = y - y0f;
        const int x0 = (int)x0f, y0 = (int)y0f;

#pragma unroll
        for (int cc = 0; cc < 4; cc++) {
            const int dx = cc & 1, dy = cc >> 1;
            const int xi = x0 + dx, yi = y0 + dy;
            const float wx = dx ? lx : (1.f - lx);
            const float wy = dy ? ly : (1.f - ly);
            const bool valid = (xi >= 0) && (xi < W) && (yi >= 0) && (yi < H);
            const int xc = min(max(xi, 0), W - 1);
            const int yc = min(max(yi, 0), H - 1);
            s_pos[qi][s][cc] = st + yc * W + xc;
            s_wt[qi][s][cc] = valid ? (wx * wy * aw) : 0.f;
        }
    }
    __syncthreads();

    const int h = tq >> 4;
    const int d2 = tq & 15;
    const int ch = h * 32 + d2 * 2;
    const __half* vb = g_vh + (size_t)b * NV * EMBED + ch;
    float2 acc = make_float2(0.f, 0.f);
#pragma unroll
    for (int i = 0; i < 16; i++) {
        const int s = h * 16 + i;
#pragma unroll
        for (int cc = 0; cc < 4; cc++) {
            const float w = s_wt[qi][s][cc];
            const __half2 hv = *reinterpret_cast<const __half2*>(vb + (size_t)s_pos[qi][s][cc] * EMBED);
            const float2 f = __half22float2(hv);
            acc.x = fmaf(w, f.x, acc.x);
            acc.y = fmaf(w, f.y, acc.y);
        }
    }
    *reinterpret_cast<float2*>(&g_attn[(size_t)q * EMBED + ch]) = acc;
}

// ---------------- launch ----------------
extern "C" void kernel_launch(void* const* d_in, const int* in_sizes, int n_in,
                              void* d_out, int out_size)
{
    const float* query  = (const float*)d_in[0];
    const float* value  = (const float*)d_in[1];
    const float* rp     = (const float*)d_in[2];
    const float* W_off  = (const float*)d_in[4];
    const float* b_off  = (const float*)d_in[5];
    const float* W_attn = (const float*)d_in[6];
    const float* b_attn = (const float*)d_in[7];
    const float* W_v    = (const float*)d_in[8];
    const float* b_v    = (const float*)d_in[9];
    const float* W_out  = (const float*)d_in[10];
    const float* b_out  = (const float*)d_in[11];
    float* out = (float*)d_out;

    float *pqa, *pattn, *pbias_qa;
    __half* pvh;
    cudaGetSymbolAddress((void**)&pvh,      g_vh);
    cudaGetSymbolAddress((void**)&pqa,      g_qa);
    cudaGetSymbolAddress((void**)&pattn,    g_attn);
    cudaGetSymbolAddress((void**)&pbias_qa, g_bias_qa);

    __half *bvh, *bvl, *bqh, *bql, *buh, *bul;
    cudaGetSymbolAddress((void**)&bvh, g_Bvh); cudaGetSymbolAddress((void**)&bvl, g_Bvl);
    cudaGetSymbolAddress((void**)&bqh, g_Bqh); cudaGetSymbolAddress((void**)&bql, g_Bql);
    cudaGetSymbolAddress((void**)&buh, g_Buh); cudaGetSymbolAddress((void**)&bul, g_Bul);

    cudaFuncSetAttribute(mma_gemm_kernel,
                         cudaFuncAttributeMaxDynamicSharedMemorySize, DSMEM_BYTES);

    static cudaStream_t s2 = nullptr;
    static cudaEvent_t evFork = nullptr, evJoin = nullptr;
    if (!s2) {
        cudaStreamCreateWithFlags(&s2, cudaStreamNonBlocking);
        cudaEventCreateWithFlags(&evFork, cudaEventDisableTiming);
        cudaEventCreateWithFlags(&evJoin, cudaEventDisableTiming);
    }

    conv_all_kernel<<<898, 256>>>(W_v, W_off, W_attn, W_out, b_off, b_attn);

    cudaEventRecord(evFork, 0);
    cudaStreamWaitEvent(s2, evFork, 0);

    {   // fused offsets+logits: (NBQ,256)@(256,384)
        dim3 grid(6, (NBQ + 127) / 128);
        mma_gemm_kernel<<<grid, 256, DSMEM_BYTES, s2>>>(query, bqh, bql, pbias_qa, nullptr,
                                                        pqa, nullptr, NBQ, 384);
    }

    const int Mv = BS * NV;
    {   // value projection -> fp16
        dim3 grid(4, (Mv + 127) / 128);
        mma_gemm_kernel<<<grid, 256, DSMEM_BYTES>>>(value, bvh, bvl, b_v, nullptr,
                                                    nullptr, pvh, Mv, 256);
    }

    cudaEventRecord(evJoin, s2);
    cudaStreamWaitEvent(0, evJoin, 0);

    msda_sample_kernel<<<NBQ / 2, 256>>>(rp);

    {   // output projection + residual
        dim3 grid(4, (NBQ + 127) / 128);
        mma_gemm_kernel<<<grid, 256, DSMEM_BYTES>>>(pattn, buh, bul, b_out, query,
                                                    out, nullptr, NBQ, 256);
    }
}

// round 10
// speedup vs baseline: 3.1438x; 1.0793x over previous
#include <cuda_runtime.h>
#include <cuda_bf16.h>
#include <cuda_fp16.h>
#include <cstdint>

// ---------------- problem constants ----------------
#define BS      8
#define NQ      900
#define EMBED   256
#define HEADS   8
#define LEVELS  4
#define POINTS  4
#define NV      13294
#define NBQ     (BS * NQ)      // 7200
#define KDIM    256

__device__ __constant__ int c_LH[4] = {100, 50, 25, 13};
__device__ __constant__ int c_LW[4] = {100, 50, 25, 13};
__device__ __constant__ int c_LS[4] = {0, 10000, 12500, 13125};

// ---------------- scratch ----------------
__device__ __half g_vh[(size_t)BS * NV * EMBED];
__device__ float g_qa[(size_t)NBQ * 384];
__device__ float g_attn[(size_t)NBQ * EMBED];
__device__ float g_bias_qa[384];

__device__ __half g_Bvh[256 * 256], g_Bvl[256 * 256];
__device__ __half g_Bqh[384 * 256], g_Bql[384 * 256];
__device__ __half g_Buh[256 * 256], g_Bul[256 * 256];

// ---------------- helpers ----------------
__device__ __forceinline__ uint32_t smem_u32(const void* p) {
    uint32_t a;
    asm("{ .reg .u64 t; cvta.to.shared.u64 t, %1; cvt.u32.u64 %0, t; }" : "=r"(a) : "l"(p));
    return a;
}
__device__ __forceinline__ uint32_t pack_h2(float x, float y) {
    __half2 h = __floats2half2_rn(x, y);
    return *reinterpret_cast<uint32_t*>(&h);
}
__device__ __forceinline__ void mma_f16(float d[4],
                                        uint32_t a0, uint32_t a1, uint32_t a2, uint32_t a3,
                                        uint32_t b0, uint32_t b1) {
    asm volatile(
        "mma.sync.aligned.m16n8k16.row.col.f32.f16.f16.f32 "
        "{%0,%1,%2,%3}, {%4,%5,%6,%7}, {%8,%9}, {%0,%1,%2,%3};"
        : "+f"(d[0]), "+f"(d[1]), "+f"(d[2]), "+f"(d[3])
        : "r"(a0), "r"(a1), "r"(a2), "r"(a3), "r"(b0), "r"(b1));
}
__device__ __forceinline__ void ldsm_x4(uint32_t& r0, uint32_t& r1, uint32_t& r2, uint32_t& r3,
                                        uint32_t addr) {
    asm volatile("ldmatrix.sync.aligned.m8n8.x4.shared.b16 {%0,%1,%2,%3}, [%4];"
                 : "=r"(r0), "=r"(r1), "=r"(r2), "=r"(r3) : "r"(addr));
}
__device__ __forceinline__ void cp_async16(uint32_t saddr, const void* gaddr) {
    asm volatile("cp.async.ca.shared.global [%0], [%1], 16;" :: "r"(saddr), "l"(gaddr));
}

// ---------------- fused weight conversion + bias pack ----------------
__global__ void conv_all_kernel(const float* __restrict__ Wv,
                                const float* __restrict__ Woff,
                                const float* __restrict__ Wattn,
                                const float* __restrict__ Wout,
                                const float* __restrict__ b_off,
                                const float* __restrict__ b_attn)
{
    int i = blockIdx.x * 256 + threadIdx.x;
    const float* W; __half *Bh, *Bl; int N, j, nbase;
    if (i < 65536)        { W = Wv;    Bh = g_Bvh; Bl = g_Bvl; N = 256; j = i;          nbase = 0; }
    else if (i < 131072)  { W = Woff;  Bh = g_Bqh; Bl = g_Bql; N = 256; j = i - 65536;  nbase = 0; }
    else if (i < 163840)  { W = Wattn; Bh = g_Bqh; Bl = g_Bql; N = 128; j = i - 131072; nbase = 256; }
    else if (i < 229376)  { W = Wout;  Bh = g_Buh; Bl = g_Bul; N = 256; j = i - 163840; nbase = 0; }
    else if (i < 229760)  {
        int j2 = i - 229376;
        g_bias_qa[j2] = (j2 < 256) ? b_off[j2] : b_attn[j2 - 256];
        return;
    } else return;
    int k = j / N, n = j % N;
    float x = W[j];
    __half hb = __float2half_rn(x);
    float lo = x - __half2float(hb);
    Bh[(size_t)(nbase + n) * KDIM + k] = hb;
    Bl[(size_t)(nbase + n) * KDIM + k] = __float2half_rn(lo);
}

// ---------------- HMMA GEMM: CTA 128x64, warp 32x32, fp16 TERMS-split -------
#define KC 32
#define ROWB 80
#define A_B 0
#define B_HI_B (128 * ROWB)
#define B_LO_B (B_HI_B + 64 * ROWB)
#define STAGE_B (B_LO_B + 64 * ROWB)
#define DSMEM_BYTES (2 * STAGE_B)

template<int TERMS>
__global__ __launch_bounds__(256, 2)
void mma_gemm_kernel(const float* __restrict__ A,
                     const __half* __restrict__ Bh,
                     const __half* __restrict__ Bl,
                     const float* __restrict__ bias,
                     const float* __restrict__ resid,
                     float* __restrict__ C,
                     __half* __restrict__ Ch,
                     int M, int Ntot)
{
    extern __shared__ char smemc[];
    __shared__ float s_bias[64];

    const int tid = threadIdx.x;
    const int wid = tid >> 5;
    const int lane = tid & 31;
    const int g = lane >> 2;
    const int tig = lane & 3;
    const int wm = wid & 3;
    const int wn = wid >> 2;
    const int m0 = blockIdx.y * 128;
    const int n0 = blockIdx.x * 64;

    if (tid < 64) s_bias[tid] = bias[n0 + tid];

    const uint32_t sbase = smem_u32(smemc);

    float acc[2][4][4];
#pragma unroll
    for (int mt = 0; mt < 2; mt++)
#pragma unroll
        for (int nt = 0; nt < 4; nt++)
#pragma unroll
            for (int q = 0; q < 4; q++) acc[mt][nt][q] = 0.f;

    const int a_row[4] = { (tid + 0) >> 3, (tid + 256) >> 3, (tid + 512) >> 3, (tid + 768) >> 3 };
    const int a_q = tid & 7;
    const int b_row0 = tid >> 2, b_c0 = tid & 3;

    const int lm_arow = lane & 15;
    const int lm_akoff = (lane >> 4) * 16;
    const int lm_brow = (lane & 7) + ((lane >> 4) << 3);
    const int lm_bkoff = ((lane >> 3) & 1) * 16;

    auto fill_A = [&](int stage, const float4* pa) {
#pragma unroll
        for (int i = 0; i < 4; i++) {
            const float4 f = pa[i];
            const uint32_t off = (uint32_t)(a_row[i] * ROWB + a_q * 8);
            *reinterpret_cast<uint2*>(smemc + stage * STAGE_B + A_B + off) =
                make_uint2(pack_h2(f.x, f.y), pack_h2(f.z, f.w));
        }
    };

    auto issue_B = [&](int stage, int k0) {
        const uint32_t Sb = sbase + stage * STAGE_B;
        cp_async16(Sb + B_HI_B + b_row0 * ROWB + b_c0 * 16,
                   Bh + (size_t)(n0 + b_row0) * KDIM + k0 + b_c0 * 8);
        if (TERMS == 2)
            cp_async16(Sb + B_LO_B + b_row0 * ROWB + b_c0 * 16,
                       Bl + (size_t)(n0 + b_row0) * KDIM + k0 + b_c0 * 8);
        asm volatile("cp.async.commit_group;" ::: "memory");
    };

    {
        issue_B(0, 0);
        float4 pa[4];
#pragma unroll
        for (int i = 0; i < 4; i++) {
            pa[i] = make_float4(0.f, 0.f, 0.f, 0.f);
            if (m0 + a_row[i] < M)
                pa[i] = *reinterpret_cast<const float4*>(&A[(size_t)(m0 + a_row[i]) * KDIM + a_q * 4]);
        }
        fill_A(0, pa);
        asm volatile("cp.async.wait_group 0;" ::: "memory");
    }
    __syncthreads();

    const int ntiles = KDIM / KC;
    int buf = 0;

    for (int kt = 0; kt < ntiles; kt++) {
        const bool more = (kt + 1 < ntiles);
        float4 pa[4];
        if (more) {
            const int k0 = (kt + 1) * KC;
            issue_B(buf ^ 1, k0);
#pragma unroll
            for (int i = 0; i < 4; i++) {
                pa[i] = make_float4(0.f, 0.f, 0.f, 0.f);
                if (m0 + a_row[i] < M)
                    pa[i] = *reinterpret_cast<const float4*>(&A[(size_t)(m0 + a_row[i]) * KDIM + k0 + a_q * 4]);
            }
        }

        const uint32_t Sb = sbase + buf * STAGE_B;
#pragma unroll
        for (int kk = 0; kk < 2; kk++) {
            uint32_t bh[4][2], bl[4][2];
#pragma unroll
            for (int p = 0; p < 2; p++) {
                const uint32_t baddr = Sb + (uint32_t)((wn * 32 + p * 16 + lm_brow) * ROWB + kk * 32 + lm_bkoff);
                ldsm_x4(bh[2 * p][0], bh[2 * p][1], bh[2 * p + 1][0], bh[2 * p + 1][1],
                        baddr + B_HI_B);
                if (TERMS == 2)
                    ldsm_x4(bl[2 * p][0], bl[2 * p][1], bl[2 * p + 1][0], bl[2 * p + 1][1],
                            baddr + B_LO_B);
            }
            uint32_t ah[2][4];
#pragma unroll
            for (int mt = 0; mt < 2; mt++) {
                const uint32_t aaddr = Sb + (uint32_t)((wm * 32 + mt * 16 + lm_arow) * ROWB + kk * 32 + lm_akoff);
                ldsm_x4(ah[mt][0], ah[mt][1], ah[mt][2], ah[mt][3], aaddr + A_B);
            }
#pragma unroll
            for (int mt = 0; mt < 2; mt++)
#pragma unroll
                for (int nt = 0; nt < 4; nt++) {
                    mma_f16(acc[mt][nt], ah[mt][0], ah[mt][1], ah[mt][2], ah[mt][3],
                            bh[nt][0], bh[nt][1]);
                    if (TERMS == 2)
                        mma_f16(acc[mt][nt], ah[mt][0], ah[mt][1], ah[mt][2], ah[mt][3],
                                bl[nt][0], bl[nt][1]);
                }
        }

        if (more) {
            fill_A(buf ^ 1, pa);
            asm volatile("cp.async.wait_group 0;" ::: "memory");
            __syncthreads();
            buf ^= 1;
        }
    }

    // ---- epilogue ----
#pragma unroll
    for (int mt = 0; mt < 2; mt++) {
        const int r0 = m0 + wm * 32 + mt * 16 + g;
        const int r1 = r0 + 8;
#pragma unroll
        for (int nt = 0; nt < 4; nt++) {
            const int cloc = wn * 32 + nt * 8 + tig * 2;
            const int col = n0 + cloc;
            const float b0 = s_bias[cloc], b1 = s_bias[cloc + 1];
            float2 v0 = make_float2(acc[mt][nt][0] + b0, acc[mt][nt][1] + b1);
            float2 v1 = make_float2(acc[mt][nt][2] + b0, acc[mt][nt][3] + b1);
            if (resid) {
                if (r0 < M) {
                    const float2 rv = *reinterpret_cast<const float2*>(&resid[(size_t)r0 * 256 + col]);
                    v0.x += rv.x; v0.y += rv.y;
                }
                if (r1 < M) {
                    const float2 rv = *reinterpret_cast<const float2*>(&resid[(size_t)r1 * 256 + col]);
                    v1.x += rv.x; v1.y += rv.y;
                }
            }
            if (Ch) {
                if (r0 < M)
                    *reinterpret_cast<__half2*>(&Ch[(size_t)r0 * Ntot + col]) = __floats2half2_rn(v0.x, v0.y);
                if (r1 < M)
                    *reinterpret_cast<__half2*>(&Ch[(size_t)r1 * Ntot + col]) = __floats2half2_rn(v1.x, v1.y);
            } else {
                if (r0 < M) *reinterpret_cast<float2*>(&C[(size_t)r0 * Ntot + col]) = v0;
                if (r1 < M) *reinterpret_cast<float2*>(&C[(size_t)r1 * Ntot + col]) = v1;
            }
        }
    }
}

// ---------------- sampling kernel: 2 queries/block, half2 gathers ----------
__global__ __launch_bounds__(256)
void msda_sample_kernel(const float* __restrict__ rp)
{
    const int tid = threadIdx.x;
    const int qi = tid >> 7;
    const int tq = tid & 127;
    const int q = blockIdx.x * 2 + qi;
    const int b = q / NQ;

    __shared__ float s_aw[2][128];
    __shared__ int   s_pos[2][128][4];
    __shared__ float s_wt[2][128][4];

    s_aw[qi][tq] = g_qa[(size_t)q * 384 + 256 + tq];
    __syncthreads();

    if (tid < 16) {
        const int sq = tid >> 3, h = tid & 7;
        float* aw = &s_aw[sq][h * 16];
        float mx = -1e30f;
#pragma unroll
        for (int i = 0; i < 16; i++) mx = fmaxf(mx, aw[i]);
        float e[16];
        float sum = 0.f;
#pragma unroll
        for (int i = 0; i < 16; i++) { e[i] = __expf(aw[i] - mx); sum += e[i]; }
        float inv = 1.f / sum;
#pragma unroll
        for (int i = 0; i < 16; i++) aw[i] = e[i] * inv;
    }
    __syncthreads();

    {
        const int s = tq;
        const int l = (s >> 2) & 3;
        const float aw = s_aw[qi][s];
        const float offx = g_qa[(size_t)q * 384 + s * 2];
        const float offy = g_qa[(size_t)q * 384 + s * 2 + 1];
        const float rx = rp[((size_t)q * LEVELS + l) * 2];
        const float ry = rp[((size_t)q * LEVELS + l) * 2 + 1];
        const int W = c_LW[l], H = c_LH[l], st = c_LS[l];

        const float locx = rx + offx / (float)W;
        const float locy = ry + offy / (float)H;
        const float x = locx * (float)W - 0.5f;
        const float y = locy * (float)H - 0.5f;
        const float x0f = floorf(x), y0f = floorf(y);
        const float lx = x - x0f, ly = y - y0f;
        const int x0 = (int)x0f, y0 = (int)y0f;

#pragma unroll
        for (int cc = 0; cc < 4; cc++) {
            const int dx = cc & 1, dy = cc >> 1;
            const int xi = x0 + dx, yi = y0 + dy;
            const float wx = dx ? lx : (1.f - lx);
            const float wy = dy ? ly : (1.f - ly);
            const bool valid = (xi >= 0) && (xi < W) && (yi >= 0) && (yi < H);
            const int xc = min(max(xi, 0), W - 1);
            const int yc = min(max(yi, 0), H - 1);
            s_pos[qi][s][cc] = st + yc * W + xc;
            s_wt[qi][s][cc] = valid ? (wx * wy * aw) : 0.f;
        }
    }
    __syncthreads();

    const int h = tq >> 4;
    const int d2 = tq & 15;
    const int ch = h * 32 + d2 * 2;
    const __half* vb = g_vh + (size_t)b * NV * EMBED + ch;
    float2 acc = make_float2(0.f, 0.f);
#pragma unroll
    for (int i = 0; i < 16; i++) {
        const int s = h * 16 + i;
#pragma unroll
        for (int cc = 0; cc < 4; cc++) {
            const float w = s_wt[qi][s][cc];
            const __half2 hv = *reinterpret_cast<const __half2*>(vb + (size_t)s_pos[qi][s][cc] * EMBED);
            const float2 f = __half22float2(hv);
            acc.x = fmaf(w, f.x, acc.x);
            acc.y = fmaf(w, f.y, acc.y);
        }
    }
    *reinterpret_cast<float2*>(&g_attn[(size_t)q * EMBED + ch]) = acc;
}

// ---------------- launch ----------------
extern "C" void kernel_launch(void* const* d_in, const int* in_sizes, int n_in,
                              void* d_out, int out_size)
{
    const float* query  = (const float*)d_in[0];
    const float* value  = (const float*)d_in[1];
    const float* rp     = (const float*)d_in[2];
    const float* W_off  = (const float*)d_in[4];
    const float* b_off  = (const float*)d_in[5];
    const float* W_attn = (const float*)d_in[6];
    const float* b_attn = (const float*)d_in[7];
    const float* W_v    = (const float*)d_in[8];
    const float* b_v    = (const float*)d_in[9];
    const float* W_out  = (const float*)d_in[10];
    const float* b_out  = (const float*)d_in[11];
    float* out = (float*)d_out;

    float *pqa, *pattn, *pbias_qa;
    __half* pvh;
    cudaGetSymbolAddress((void**)&pvh,      g_vh);
    cudaGetSymbolAddress((void**)&pqa,      g_qa);
    cudaGetSymbolAddress((void**)&pattn,    g_attn);
    cudaGetSymbolAddress((void**)&pbias_qa, g_bias_qa);

    __half *bvh, *bvl, *bqh, *bql, *buh, *bul;
    cudaGetSymbolAddress((void**)&bvh, g_Bvh); cudaGetSymbolAddress((void**)&bvl, g_Bvl);
    cudaGetSymbolAddress((void**)&bqh, g_Bqh); cudaGetSymbolAddress((void**)&bql, g_Bql);
    cudaGetSymbolAddress((void**)&buh, g_Buh); cudaGetSymbolAddress((void**)&bul, g_Bul);

    cudaFuncSetAttribute(mma_gemm_kernel<1>,
                         cudaFuncAttributeMaxDynamicSharedMemorySize, DSMEM_BYTES);
    cudaFuncSetAttribute(mma_gemm_kernel<2>,
                         cudaFuncAttributeMaxDynamicSharedMemorySize, DSMEM_BYTES);

    static cudaStream_t s2 = nullptr;
    static cudaEvent_t evFork = nullptr, evJoin = nullptr;
    if (!s2) {
        cudaStreamCreateWithFlags(&s2, cudaStreamNonBlocking);
        cudaEventCreateWithFlags(&evFork, cudaEventDisableTiming);
        cudaEventCreateWithFlags(&evJoin, cudaEventDisableTiming);
    }

    conv_all_kernel<<<898, 256>>>(W_v, W_off, W_attn, W_out, b_off, b_attn);

    cudaEventRecord(evFork, 0);
    cudaStreamWaitEvent(s2, evFork, 0);

    {   // fused offsets+logits: 2-term (accuracy-sensitive, hidden behind value GEMM)
        dim3 grid(6, (NBQ + 127) / 128);
        mma_gemm_kernel<2><<<grid, 256, DSMEM_BYTES, s2>>>(query, bqh, bql, pbias_qa, nullptr,
                                                           pqa, nullptr, NBQ, 384);
    }

    const int Mv = BS * NV;
    {   // value projection -> fp16, single-term (dominant cost; error attenuated)
        dim3 grid(4, (Mv + 127) / 128);
        mma_gemm_kernel<1><<<grid, 256, DSMEM_BYTES>>>(value, bvh, bvl, b_v, nullptr,
                                                       nullptr, pvh, Mv, 256);
    }

    cudaEventRecord(evJoin, s2);
    cudaStreamWaitEvent(0, evJoin, 0);

    msda_sample_kernel<<<NBQ / 2, 256>>>(rp);

    {   // output projection + residual: 2-term
        dim3 grid(4, (NBQ + 127) / 128);
        mma_gemm_kernel<2><<<grid, 256, DSMEM_BYTES>>>(pattn, buh, bul, b_out, query,
                                                       out, nullptr, NBQ, 256);
    }
}

// round 11
// speedup vs baseline: 3.7758x; 1.2010x over previous
#include <cuda_runtime.h>
#include <cuda_bf16.h>
#include <cuda_fp16.h>
#include <cstdint>

// ---------------- problem constants ----------------
#define BS      8
#define NQ      900
#define EMBED   256
#define HEADS   8
#define LEVELS  4
#define POINTS  4
#define NV      13294
#define NBQ     (BS * NQ)      // 7200
#define KDIM    256

__device__ __constant__ int c_LH[4] = {100, 50, 25, 13};
__device__ __constant__ int c_LW[4] = {100, 50, 25, 13};
__device__ __constant__ int c_LS[4] = {0, 10000, 12500, 13125};

// ---------------- scratch ----------------
__device__ __half g_vh[(size_t)BS * NV * EMBED];
__device__ float g_qa[(size_t)NBQ * 384];
__device__ float g_attn[(size_t)NBQ * EMBED];
__device__ float g_bias_qa[384];

__device__ __half g_Bvh[256 * 256], g_Bvl[256 * 256];
__device__ __half g_Bqh[384 * 256], g_Bql[384 * 256];
__device__ __half g_Buh[256 * 256], g_Bul[256 * 256];

// ---------------- helpers ----------------
__device__ __forceinline__ uint32_t smem_u32(const void* p) {
    uint32_t a;
    asm("{ .reg .u64 t; cvta.to.shared.u64 t, %1; cvt.u32.u64 %0, t; }" : "=r"(a) : "l"(p));
    return a;
}
__device__ __forceinline__ uint32_t pack_h2(float x, float y) {
    __half2 h = __floats2half2_rn(x, y);
    return *reinterpret_cast<uint32_t*>(&h);
}
__device__ __forceinline__ void mma_f16(float d[4],
                                        uint32_t a0, uint32_t a1, uint32_t a2, uint32_t a3,
                                        uint32_t b0, uint32_t b1) {
    asm volatile(
        "mma.sync.aligned.m16n8k16.row.col.f32.f16.f16.f32 "
        "{%0,%1,%2,%3}, {%4,%5,%6,%7}, {%8,%9}, {%0,%1,%2,%3};"
        : "+f"(d[0]), "+f"(d[1]), "+f"(d[2]), "+f"(d[3])
        : "r"(a0), "r"(a1), "r"(a2), "r"(a3), "r"(b0), "r"(b1));
}
__device__ __forceinline__ void ldsm_x4(uint32_t& r0, uint32_t& r1, uint32_t& r2, uint32_t& r3,
                                        uint32_t addr) {
    asm volatile("ldmatrix.sync.aligned.m8n8.x4.shared.b16 {%0,%1,%2,%3}, [%4];"
                 : "=r"(r0), "=r"(r1), "=r"(r2), "=r"(r3) : "r"(addr));
}
__device__ __forceinline__ void cp_async16(uint32_t saddr, const void* gaddr) {
    asm volatile("cp.async.ca.shared.global [%0], [%1], 16;" :: "r"(saddr), "l"(gaddr));
}

// ---------------- fused weight conversion + bias pack ----------------
__global__ void conv_all_kernel(const float* __restrict__ Wv,
                                const float* __restrict__ Woff,
                                const float* __restrict__ Wattn,
                                const float* __restrict__ Wout,
                                const float* __restrict__ b_off,
                                const float* __restrict__ b_attn)
{
    int i = blockIdx.x * 256 + threadIdx.x;
    const float* W; __half *Bh, *Bl; int N, j, nbase;
    if (i < 65536)        { W = Wv;    Bh = g_Bvh; Bl = g_Bvl; N = 256; j = i;          nbase = 0; }
    else if (i < 131072)  { W = Woff;  Bh = g_Bqh; Bl = g_Bql; N = 256; j = i - 65536;  nbase = 0; }
    else if (i < 163840)  { W = Wattn; Bh = g_Bqh; Bl = g_Bql; N = 128; j = i - 131072; nbase = 256; }
    else if (i < 229376)  { W = Wout;  Bh = g_Buh; Bl = g_Bul; N = 256; j = i - 163840; nbase = 0; }
    else if (i < 229760)  {
        int j2 = i - 229376;
        g_bias_qa[j2] = (j2 < 256) ? b_off[j2] : b_attn[j2 - 256];
        return;
    } else return;
    int k = j / N, n = j % N;
    float x = W[j];
    __half hb = __float2half_rn(x);
    float lo = x - __half2float(hb);
    Bh[(size_t)(nbase + n) * KDIM + k] = hb;
    Bl[(size_t)(nbase + n) * KDIM + k] = __float2half_rn(lo);
}

// ---------------- HMMA GEMM: CTA 128xBN, warp 32x(BN/2), fp16 TERMS-split ---
#define KC 32
#define ROWB 80

template<int TERMS, int BN>
__global__ __launch_bounds__(256, 2)
void mma_gemm_kernel(const float* __restrict__ A,
                     const __half* __restrict__ Bh,
                     const __half* __restrict__ Bl,
                     const float* __restrict__ bias,
                     const float* __restrict__ resid,
                     float* __restrict__ C,
                     __half* __restrict__ Ch,
                     int M, int Ntot)
{
    constexpr int A_B    = 0;
    constexpr int B_HI_B = 128 * ROWB;
    constexpr int B_LO_B = B_HI_B + BN * ROWB;
    constexpr int STAGE  = B_LO_B + BN * ROWB;
    constexpr int NTC    = BN / 16;          // n-fragments per warp

    extern __shared__ char smemc[];
    __shared__ float s_bias[BN];

    const int tid = threadIdx.x;
    const int wid = tid >> 5;
    const int lane = tid & 31;
    const int g = lane >> 2;
    const int tig = lane & 3;
    const int wm = wid & 3;
    const int wn = wid >> 2;
    const int m0 = blockIdx.y * 128;
    const int n0 = blockIdx.x * BN;

    if (tid < BN) s_bias[tid] = bias[n0 + tid];

    const uint32_t sbase = smem_u32(smemc);

    float acc[2][NTC][4];
#pragma unroll
    for (int mt = 0; mt < 2; mt++)
#pragma unroll
        for (int nt = 0; nt < NTC; nt++)
#pragma unroll
            for (int q = 0; q < 4; q++) acc[mt][nt][q] = 0.f;

    const int a_row[4] = { (tid + 0) >> 3, (tid + 256) >> 3, (tid + 512) >> 3, (tid + 768) >> 3 };
    const int a_q = tid & 7;

    const int lm_arow = lane & 15;
    const int lm_akoff = (lane >> 4) * 16;
    const int lm_brow = (lane & 7) + ((lane >> 4) << 3);
    const int lm_bkoff = ((lane >> 3) & 1) * 16;

    auto fill_A = [&](int stage, const float4* pa) {
#pragma unroll
        for (int i = 0; i < 4; i++) {
            const float4 f = pa[i];
            const uint32_t off = (uint32_t)(a_row[i] * ROWB + a_q * 8);
            *reinterpret_cast<uint2*>(smemc + stage * STAGE + A_B + off) =
                make_uint2(pack_h2(f.x, f.y), pack_h2(f.z, f.w));
        }
    };

    auto issue_B = [&](int stage, int k0) {
        const uint32_t Sb = sbase + stage * STAGE;
#pragma unroll
        for (int u = tid; u < BN * 4; u += 256) {
            const int row = u >> 2, c = u & 3;
            cp_async16(Sb + B_HI_B + row * ROWB + c * 16,
                       Bh + (size_t)(n0 + row) * KDIM + k0 + c * 8);
            if (TERMS == 2)
                cp_async16(Sb + B_LO_B + row * ROWB + c * 16,
                           Bl + (size_t)(n0 + row) * KDIM + k0 + c * 8);
        }
        asm volatile("cp.async.commit_group;" ::: "memory");
    };

    {
        issue_B(0, 0);
        float4 pa[4];
#pragma unroll
        for (int i = 0; i < 4; i++) {
            pa[i] = make_float4(0.f, 0.f, 0.f, 0.f);
            if (m0 + a_row[i] < M)
                pa[i] = *reinterpret_cast<const float4*>(&A[(size_t)(m0 + a_row[i]) * KDIM + a_q * 4]);
        }
        fill_A(0, pa);
        asm volatile("cp.async.wait_group 0;" ::: "memory");
    }
    __syncthreads();

    const int ntiles = KDIM / KC;
    int buf = 0;

    for (int kt = 0; kt < ntiles; kt++) {
        const bool more = (kt + 1 < ntiles);
        float4 pa[4];
        if (more) {
            const int k0 = (kt + 1) * KC;
            issue_B(buf ^ 1, k0);
#pragma unroll
            for (int i = 0; i < 4; i++) {
                pa[i] = make_float4(0.f, 0.f, 0.f, 0.f);
                if (m0 + a_row[i] < M)
                    pa[i] = *reinterpret_cast<const float4*>(&A[(size_t)(m0 + a_row[i]) * KDIM + k0 + a_q * 4]);
            }
        }

        const uint32_t Sb = sbase + buf * STAGE;
#pragma unroll
        for (int kk = 0; kk < 2; kk++) {
            uint32_t bh[NTC][2], bl[NTC][2];
#pragma unroll
            for (int p = 0; p < NTC / 2; p++) {
                const uint32_t baddr = Sb + (uint32_t)((wn * (BN / 2) + p * 16 + lm_brow) * ROWB + kk * 32 + lm_bkoff);
                ldsm_x4(bh[2 * p][0], bh[2 * p][1], bh[2 * p + 1][0], bh[2 * p + 1][1],
                        baddr + B_HI_B);
                if (TERMS == 2)
                    ldsm_x4(bl[2 * p][0], bl[2 * p][1], bl[2 * p + 1][0], bl[2 * p + 1][1],
                            baddr + B_LO_B);
            }
            uint32_t ah[2][4];
#pragma unroll
            for (int mt = 0; mt < 2; mt++) {
                const uint32_t aaddr = Sb + (uint32_t)((wm * 32 + mt * 16 + lm_arow) * ROWB + kk * 32 + lm_akoff);
                ldsm_x4(ah[mt][0], ah[mt][1], ah[mt][2], ah[mt][3], aaddr + A_B);
            }
#pragma unroll
            for (int mt = 0; mt < 2; mt++)
#pragma unroll
                for (int nt = 0; nt < NTC; nt++) {
                    mma_f16(acc[mt][nt], ah[mt][0], ah[mt][1], ah[mt][2], ah[mt][3],
                            bh[nt][0], bh[nt][1]);
                    if (TERMS == 2)
                        mma_f16(acc[mt][nt], ah[mt][0], ah[mt][1], ah[mt][2], ah[mt][3],
                                bl[nt][0], bl[nt][1]);
                }
        }

        if (more) {
            fill_A(buf ^ 1, pa);
            asm volatile("cp.async.wait_group 0;" ::: "memory");
            __syncthreads();
            buf ^= 1;
        }
    }

    // ---- epilogue ----
#pragma unroll
    for (int mt = 0; mt < 2; mt++) {
        const int r0 = m0 + wm * 32 + mt * 16 + g;
        const int r1 = r0 + 8;
#pragma unroll
        for (int nt = 0; nt < NTC; nt++) {
            const int cloc = wn * (BN / 2) + nt * 8 + tig * 2;
            const int col = n0 + cloc;
            const float b0 = s_bias[cloc], b1 = s_bias[cloc + 1];
            float2 v0 = make_float2(acc[mt][nt][0] + b0, acc[mt][nt][1] + b1);
            float2 v1 = make_float2(acc[mt][nt][2] + b0, acc[mt][nt][3] + b1);
            if (resid) {
                if (r0 < M) {
                    const float2 rv = *reinterpret_cast<const float2*>(&resid[(size_t)r0 * 256 + col]);
                    v0.x += rv.x; v0.y += rv.y;
                }
                if (r1 < M) {
                    const float2 rv = *reinterpret_cast<const float2*>(&resid[(size_t)r1 * 256 + col]);
                    v1.x += rv.x; v1.y += rv.y;
                }
            }
            if (Ch) {
                if (r0 < M)
                    *reinterpret_cast<__half2*>(&Ch[(size_t)r0 * Ntot + col]) = __floats2half2_rn(v0.x, v0.y);
                if (r1 < M)
                    *reinterpret_cast<__half2*>(&Ch[(size_t)r1 * Ntot + col]) = __floats2half2_rn(v1.x, v1.y);
            } else {
                if (r0 < M) *reinterpret_cast<float2*>(&C[(size_t)r0 * Ntot + col]) = v0;
                if (r1 < M) *reinterpret_cast<float2*>(&C[(size_t)r1 * Ntot + col]) = v1;
            }
        }
    }
}

// ---------------- sampling kernel: 2 queries/block, half2 gathers ----------
__global__ __launch_bounds__(256)
void msda_sample_kernel(const float* __restrict__ rp)
{
    const int tid = threadIdx.x;
    const int qi = tid >> 7;
    const int tq = tid & 127;
    const int q = blockIdx.x * 2 + qi;
    const int b = q / NQ;

    __shared__ float s_aw[2][128];
    __shared__ int   s_pos[2][128][4];
    __shared__ float s_wt[2][128][4];

    s_aw[qi][tq] = g_qa[(size_t)q * 384 + 256 + tq];
    __syncthreads();

    if (tid < 16) {
        const int sq = tid >> 3, h = tid & 7;
        float* aw = &s_aw[sq][h * 16];
        float mx = -1e30f;
#pragma unroll
        for (int i = 0; i < 16; i++) mx = fmaxf(mx, aw[i]);
        float e[16];
        float sum = 0.f;
#pragma unroll
        for (int i = 0; i < 16; i++) { e[i] = __expf(aw[i] - mx); sum += e[i]; }
        float inv = 1.f / sum;
#pragma unroll
        for (int i = 0; i < 16; i++) aw[i] = e[i] * inv;
    }
    __syncthreads();

    {
        const int s = tq;
        const int l = (s >> 2) & 3;
        const float aw = s_aw[qi][s];
        const float offx = g_qa[(size_t)q * 384 + s * 2];
        const float offy = g_qa[(size_t)q * 384 + s * 2 + 1];
        const float rx = rp[((size_t)q * LEVELS + l) * 2];
        const float ry = rp[((size_t)q * LEVELS + l) * 2 + 1];
        const int W = c_LW[l], H = c_LH[l], st = c_LS[l];

        const float locx = rx + offx / (float)W;
        const float locy = ry + offy / (float)H;
        const float x = locx * (float)W - 0.5f;
        const float y = locy * (float)H - 0.5f;
        const float x0f = floorf(x), y0f = floorf(y);
        const float lx = x - x0f, ly = y - y0f;
        const int x0 = (int)x0f, y0 = (int)y0f;

#pragma unroll
        for (int cc = 0; cc < 4; cc++) {
            const int dx = cc & 1, dy = cc >> 1;
            const int xi = x0 + dx, yi = y0 + dy;
            const float wx = dx ? lx : (1.f - lx);
            const float wy = dy ? ly : (1.f - ly);
            const bool valid = (xi >= 0) && (xi < W) && (yi >= 0) && (yi < H);
            const int xc = min(max(xi, 0), W - 1);
            const int yc = min(max(yi, 0), H - 1);
            s_pos[qi][s][cc] = st + yc * W + xc;
            s_wt[qi][s][cc] = valid ? (wx * wy * aw) : 0.f;
        }
    }
    __syncthreads();

    const int h = tq >> 4;
    const int d2 = tq & 15;
    const int ch = h * 32 + d2 * 2;
    const __half* vb = g_vh + (size_t)b * NV * EMBED + ch;
    float2 acc = make_float2(0.f, 0.f);
#pragma unroll
    for (int i = 0; i < 16; i++) {
        const int s = h * 16 + i;
#pragma unroll
        for (int cc = 0; cc < 4; cc++) {
            const float w = s_wt[qi][s][cc];
            const __half2 hv = *reinterpret_cast<const __half2*>(vb + (size_t)s_pos[qi][s][cc] * EMBED);
            const float2 f = __half22float2(hv);
            acc.x = fmaf(w, f.x, acc.x);
            acc.y = fmaf(w, f.y, acc.y);
        }
    }
    *reinterpret_cast<float2*>(&g_attn[(size_t)q * EMBED + ch]) = acc;
}

// ---------------- launch ----------------
extern "C" void kernel_launch(void* const* d_in, const int* in_sizes, int n_in,
                              void* d_out, int out_size)
{
    const float* query  = (const float*)d_in[0];
    const float* value  = (const float*)d_in[1];
    const float* rp     = (const float*)d_in[2];
    const float* W_off  = (const float*)d_in[4];
    const float* b_off  = (const float*)d_in[5];
    const float* W_attn = (const float*)d_in[6];
    const float* b_attn = (const float*)d_in[7];
    const float* W_v    = (const float*)d_in[8];
    const float* b_v    = (const float*)d_in[9];
    const float* W_out  = (const float*)d_in[10];
    const float* b_out  = (const float*)d_in[11];
    float* out = (float*)d_out;

    float *pqa, *pattn, *pbias_qa;
    __half* pvh;
    cudaGetSymbolAddress((void**)&pvh,      g_vh);
    cudaGetSymbolAddress((void**)&pqa,      g_qa);
    cudaGetSymbolAddress((void**)&pattn,    g_attn);
    cudaGetSymbolAddress((void**)&pbias_qa, g_bias_qa);

    __half *bvh, *bvl, *bqh, *bql, *buh, *bul;
    cudaGetSymbolAddress((void**)&bvh, g_Bvh); cudaGetSymbolAddress((void**)&bvl, g_Bvl);
    cudaGetSymbolAddress((void**)&bqh, g_Bqh); cudaGetSymbolAddress((void**)&bql, g_Bql);
    cudaGetSymbolAddress((void**)&buh, g_Buh); cudaGetSymbolAddress((void**)&bul, g_Bul);

    const int DS64  = 2 * ((128 + 2 * 64) * ROWB);    // 40960
    const int DS128 = 2 * ((128 + 2 * 128) * ROWB);   // 61440
    cudaFuncSetAttribute(mma_gemm_kernel<2, 64>,
                         cudaFuncAttributeMaxDynamicSharedMemorySize, DS64);
    cudaFuncSetAttribute(mma_gemm_kernel<1, 128>,
                         cudaFuncAttributeMaxDynamicSharedMemorySize, DS128);

    static cudaStream_t s2 = nullptr;
    static cudaEvent_t evFork = nullptr, evJoin = nullptr;
    if (!s2) {
        cudaStreamCreateWithFlags(&s2, cudaStreamNonBlocking);
        cudaEventCreateWithFlags(&evFork, cudaEventDisableTiming);
        cudaEventCreateWithFlags(&evJoin, cudaEventDisableTiming);
    }

    conv_all_kernel<<<898, 256>>>(W_v, W_off, W_attn, W_out, b_off, b_attn);

    cudaEventRecord(evFork, 0);
    cudaStreamWaitEvent(s2, evFork, 0);

    {   // fused offsets+logits: 2-term, BN=64 (hidden behind value GEMM)
        dim3 grid(6, (NBQ + 127) / 128);
        mma_gemm_kernel<2, 64><<<grid, 256, DS64, s2>>>(query, bqh, bql, pbias_qa, nullptr,
                                                        pqa, nullptr, NBQ, 384);
    }

    const int Mv = BS * NV;
    {   // value projection -> fp16, 1-term, BN=128 (halved A/B L2 traffic)
        dim3 grid(2, (Mv + 127) / 128);
        mma_gemm_kernel<1, 128><<<grid, 256, DS128>>>(value, bvh, bvl, b_v, nullptr,
                                                      nullptr, pvh, Mv, 256);
    }

    cudaEventRecord(evJoin, s2);
    cudaStreamWaitEvent(0, evJoin, 0);

    msda_sample_kernel<<<NBQ / 2, 256>>>(rp);

    {   // output projection + residual: 2-term, BN=64
        dim3 grid(4, (NBQ + 127) / 128);
        mma_gemm_kernel<2, 64><<<grid, 256, DS64>>>(pattn, buh, bul, b_out, query,
                                                    out, nullptr, NBQ, 256);
    }
}

// round 13
// speedup vs baseline: 3.7832x; 1.0020x over previous
#include <cuda_runtime.h>
#include <cuda_bf16.h>
#include <cuda_fp16.h>
#include <cstdint>

// ---------------- problem constants ----------------
#define BS      8
#define NQ      900
#define EMBED   256
#define HEADS   8
#define LEVELS  4
#define POINTS  4
#define NV      13294
#define NBQ     (BS * NQ)      // 7200
#define KDIM    256

__device__ __constant__ int c_LH[4] = {100, 50, 25, 13};
__device__ __constant__ int c_LW[4] = {100, 50, 25, 13};
__device__ __constant__ int c_LS[4] = {0, 10000, 12500, 13125};

// ---------------- scratch ----------------
__device__ __half g_vh[(size_t)BS * NV * EMBED];
__device__ float g_qa[(size_t)NBQ * 384];
__device__ float g_attn[(size_t)NBQ * EMBED];
__device__ float g_bias_qa[384];

__device__ __half g_Bvh[256 * 256], g_Bvl[256 * 256];
__device__ __half g_Bqh[384 * 256], g_Bql[384 * 256];
__device__ __half g_Buh[256 * 256], g_Bul[256 * 256];

// ---------------- helpers ----------------
__device__ __forceinline__ uint32_t smem_u32(const void* p) {
    uint32_t a;
    asm("{ .reg .u64 t; cvta.to.shared.u64 t, %1; cvt.u32.u64 %0, t; }" : "=r"(a) : "l"(p));
    return a;
}
__device__ __forceinline__ uint32_t pack_h2(float x, float y) {
    __half2 h = __floats2half2_rn(x, y);
    return *reinterpret_cast<uint32_t*>(&h);
}
__device__ __forceinline__ void mma_f16(float d[4],
                                        uint32_t a0, uint32_t a1, uint32_t a2, uint32_t a3,
                                        uint32_t b0, uint32_t b1) {
    asm volatile(
        "mma.sync.aligned.m16n8k16.row.col.f32.f16.f16.f32 "
        "{%0,%1,%2,%3}, {%4,%5,%6,%7}, {%8,%9}, {%0,%1,%2,%3};"
        : "+f"(d[0]), "+f"(d[1]), "+f"(d[2]), "+f"(d[3])
        : "r"(a0), "r"(a1), "r"(a2), "r"(a3), "r"(b0), "r"(b1));
}
__device__ __forceinline__ void ldsm_x4(uint32_t& r0, uint32_t& r1, uint32_t& r2, uint32_t& r3,
                                        uint32_t addr) {
    asm volatile("ldmatrix.sync.aligned.m8n8.x4.shared.b16 {%0,%1,%2,%3}, [%4];"
                 : "=r"(r0), "=r"(r1), "=r"(r2), "=r"(r3) : "r"(addr));
}
__device__ __forceinline__ void cp_async16(uint32_t saddr, const void* gaddr) {
    asm volatile("cp.async.ca.shared.global [%0], [%1], 16;" :: "r"(saddr), "l"(gaddr));
}

// ---------------- weight conversion kernels (split per stream) --------------
__device__ __forceinline__ void conv_one(const float* __restrict__ W,
                                         __half* __restrict__ Bh,
                                         __half* __restrict__ Bl,
                                         int N, int j, int nbase) {
    int k = j / N, n = j % N;
    float x = W[j];
    __half hb = __float2half_rn(x);
    float lo = x - __half2float(hb);
    Bh[(size_t)(nbase + n) * KDIM + k] = hb;
    Bl[(size_t)(nbase + n) * KDIM + k] = __float2half_rn(lo);
}

__global__ void conv_v_kernel(const float* __restrict__ Wv) {
    int i = blockIdx.x * 256 + threadIdx.x;
    if (i < 65536) conv_one(Wv, g_Bvh, g_Bvl, 256, i, 0);
}

__global__ void conv_rest_kernel(const float* __restrict__ Woff,
                                 const float* __restrict__ Wattn,
                                 const float* __restrict__ Wout,
                                 const float* __restrict__ b_off,
                                 const float* __restrict__ b_attn) {
    int i = blockIdx.x * 256 + threadIdx.x;
    if (i < 65536)        conv_one(Woff,  g_Bqh, g_Bql, 256, i, 0);
    else if (i < 98304)   conv_one(Wattn, g_Bqh, g_Bql, 128, i - 65536, 256);
    else if (i < 163840)  conv_one(Wout,  g_Buh, g_Bul, 256, i - 98304, 0);
    else if (i < 164224) {
        int j2 = i - 163840;
        g_bias_qa[j2] = (j2 < 256) ? b_off[j2] : b_attn[j2 - 256];
    }
}

// ---------------- HMMA GEMM: CTA 128xBN, warp 32x(BN/2), fp16 TERMS-split ---
#define KC 32
#define ROWB 80

template<int TERMS, int BN, int OCC>
__global__ __launch_bounds__(256, OCC)
void mma_gemm_kernel(const float* __restrict__ A,
                     const __half* __restrict__ Bh,
                     const __half* __restrict__ Bl,
                     const float* __restrict__ bias,
                     const float* __restrict__ resid,
                     float* __restrict__ C,
                     __half* __restrict__ Ch,
                     int M, int Ntot)
{
    constexpr int A_B    = 0;
    constexpr int B_HI_B = 128 * ROWB;
    constexpr int B_LO_B = B_HI_B + BN * ROWB;          // only valid if TERMS==2
    constexpr int STAGE  = B_HI_B + TERMS * BN * ROWB;
    constexpr int NTC    = BN / 16;

    extern __shared__ char smemc[];
    __shared__ float s_bias[BN];

    const int tid = threadIdx.x;
    const int wid = tid >> 5;
    const int lane = tid & 31;
    const int g = lane >> 2;
    const int tig = lane & 3;
    const int wm = wid & 3;
    const int wn = wid >> 2;
    const int m0 = blockIdx.y * 128;
    const int n0 = blockIdx.x * BN;

    if (tid < BN) s_bias[tid] = bias[n0 + tid];

    const uint32_t sbase = smem_u32(smemc);

    float acc[2][NTC][4];
#pragma unroll
    for (int mt = 0; mt < 2; mt++)
#pragma unroll
        for (int nt = 0; nt < NTC; nt++)
#pragma unroll
            for (int q = 0; q < 4; q++) acc[mt][nt][q] = 0.f;

    const int a_row[4] = { (tid + 0) >> 3, (tid + 256) >> 3, (tid + 512) >> 3, (tid + 768) >> 3 };
    const int a_q = tid & 7;

    const int lm_arow = lane & 15;
    const int lm_akoff = (lane >> 4) * 16;
    const int lm_brow = (lane & 7) + ((lane >> 4) << 3);
    const int lm_bkoff = ((lane >> 3) & 1) * 16;

    auto fill_A = [&](int stage, const float4* pa) {
#pragma unroll
        for (int i = 0; i < 4; i++) {
            const float4 f = pa[i];
            const uint32_t off = (uint32_t)(a_row[i] * ROWB + a_q * 8);
            *reinterpret_cast<uint2*>(smemc + stage * STAGE + A_B + off) =
                make_uint2(pack_h2(f.x, f.y), pack_h2(f.z, f.w));
        }
    };

    auto issue_B = [&](int stage, int k0) {
        const uint32_t Sb = sbase + stage * STAGE;
#pragma unroll
        for (int u = tid; u < BN * 4; u += 256) {
            const int row = u >> 2, c = u & 3;
            cp_async16(Sb + B_HI_B + row * ROWB + c * 16,
                       Bh + (size_t)(n0 + row) * KDIM + k0 + c * 8);
            if (TERMS == 2)
                cp_async16(Sb + B_LO_B + row * ROWB + c * 16,
                           Bl + (size_t)(n0 + row) * KDIM + k0 + c * 8);
        }
        asm volatile("cp.async.commit_group;" ::: "memory");
    };

    {
        issue_B(0, 0);
        float4 pa[4];
#pragma unroll
        for (int i = 0; i < 4; i++) {
            pa[i] = make_float4(0.f, 0.f, 0.f, 0.f);
            if (m0 + a_row[i] < M)
                pa[i] = *reinterpret_cast<const float4*>(&A[(size_t)(m0 + a_row[i]) * KDIM + a_q * 4]);
        }
        fill_A(0, pa);
        asm volatile("cp.async.wait_group 0;" ::: "memory");
    }
    __syncthreads();

    const int ntiles = KDIM / KC;
    int buf = 0;

    for (int kt = 0; kt < ntiles; kt++) {
        const bool more = (kt + 1 < ntiles);
        float4 pa[4];
        if (more) {
            const int k0 = (kt + 1) * KC;
            issue_B(buf ^ 1, k0);
#pragma unroll
            for (int i = 0; i < 4; i++) {
                pa[i] = make_float4(0.f, 0.f, 0.f, 0.f);
                if (m0 + a_row[i] < M)
                    pa[i] = *reinterpret_cast<const float4*>(&A[(size_t)(m0 + a_row[i]) * KDIM + k0 + a_q * 4]);
            }
        }

        const uint32_t Sb = sbase + buf * STAGE;
#pragma unroll
        for (int kk = 0; kk < 2; kk++) {
            uint32_t bh[NTC][2], bl[NTC][2];
#pragma unroll
            for (int p = 0; p < NTC / 2; p++) {
                const uint32_t baddr = Sb + (uint32_t)((wn * (BN / 2) + p * 16 + lm_brow) * ROWB + kk * 32 + lm_bkoff);
                ldsm_x4(bh[2 * p][0], bh[2 * p][1], bh[2 * p + 1][0], bh[2 * p + 1][1],
                        baddr + B_HI_B);
                if (TERMS == 2)
                    ldsm_x4(bl[2 * p][0], bl[2 * p][1], bl[2 * p + 1][0], bl[2 * p + 1][1],
                            baddr + B_LO_B);
            }
            uint32_t ah[2][4];
#pragma unroll
            for (int mt = 0; mt < 2; mt++) {
                const uint32_t aaddr = Sb + (uint32_t)((wm * 32 + mt * 16 + lm_arow) * ROWB + kk * 32 + lm_akoff);
                ldsm_x4(ah[mt][0], ah[mt][1], ah[mt][2], ah[mt][3], aaddr + A_B);
            }
#pragma unroll
            for (int mt = 0; mt < 2; mt++)
#pragma unroll
                for (int nt = 0; nt < NTC; nt++) {
                    mma_f16(acc[mt][nt], ah[mt][0], ah[mt][1], ah[mt][2], ah[mt][3],
                            bh[nt][0], bh[nt][1]);
                    if (TERMS == 2)
                        mma_f16(acc[mt][nt], ah[mt][0], ah[mt][1], ah[mt][2], ah[mt][3],
                                bl[nt][0], bl[nt][1]);
                }
        }

        if (more) {
            fill_A(buf ^ 1, pa);
            asm volatile("cp.async.wait_group 0;" ::: "memory");
            __syncthreads();
            buf ^= 1;
        }
    }

    // ---- epilogue ----
#pragma unroll
    for (int mt = 0; mt < 2; mt++) {
        const int r0 = m0 + wm * 32 + mt * 16 + g;
        const int r1 = r0 + 8;
#pragma unroll
        for (int nt = 0; nt < NTC; nt++) {
            const int cloc = wn * (BN / 2) + nt * 8 + tig * 2;
            const int col = n0 + cloc;
            const float b0 = s_bias[cloc], b1 = s_bias[cloc + 1];
            float2 v0 = make_float2(acc[mt][nt][0] + b0, acc[mt][nt][1] + b1);
            float2 v1 = make_float2(acc[mt][nt][2] + b0, acc[mt][nt][3] + b1);
            if (resid) {
                if (r0 < M) {
                    const float2 rv = *reinterpret_cast<const float2*>(&resid[(size_t)r0 * 256 + col]);
                    v0.x += rv.x; v0.y += rv.y;
                }
                if (r1 < M) {
                    const float2 rv = *reinterpret_cast<const float2*>(&resid[(size_t)r1 * 256 + col]);
                    v1.x += rv.x; v1.y += rv.y;
                }
            }
            if (Ch) {
                if (r0 < M)
                    *reinterpret_cast<__half2*>(&Ch[(size_t)r0 * Ntot + col]) = __floats2half2_rn(v0.x, v0.y);
                if (r1 < M)
                    *reinterpret_cast<__half2*>(&Ch[(size_t)r1 * Ntot + col]) = __floats2half2_rn(v1.x, v1.y);
            } else {
                if (r0 < M) *reinterpret_cast<float2*>(&C[(size_t)r0 * Ntot + col]) = v0;
                if (r1 < M) *reinterpret_cast<float2*>(&C[(size_t)r1 * Ntot + col]) = v1;
            }
        }
    }
}

// ---------------- sampling kernel: 2 queries/block, half2 gathers ----------
__global__ __launch_bounds__(256)
void msda_sample_kernel(const float* __restrict__ rp)
{
    const int tid = threadIdx.x;
    const int qi = tid >> 7;
    const int tq = tid & 127;
    const int q = blockIdx.x * 2 + qi;
    const int b = q / NQ;

    __shared__ float s_aw[2][128];
    __shared__ int   s_pos[2][128][4];
    __shared__ float s_wt[2][128][4];

    s_aw[qi][tq] = g_qa[(size_t)q * 384 + 256 + tq];
    __syncthreads();

    if (tid < 16) {
        const int sq = tid >> 3, h = tid & 7;
        float* aw = &s_aw[sq][h * 16];
        float mx = -1e30f;
#pragma unroll
        for (int i = 0; i < 16; i++) mx = fmaxf(mx, aw[i]);
        float e[16];
        float sum = 0.f;
#pragma unroll
        for (int i = 0; i < 16; i++) { e[i] = __expf(aw[i] - mx); sum += e[i]; }
        float inv = 1.f / sum;
#pragma unroll
        for (int i = 0; i < 16; i++) aw[i] = e[i] * inv;
    }
    __syncthreads();

    {
        const int s = tq;
        const int l = (s >> 2) & 3;
        const float aw = s_aw[qi][s];
        const float offx = g_qa[(size_t)q * 384 + s * 2];
        const float offy = g_qa[(size_t)q * 384 + s * 2 + 1];
        const float rx = rp[((size_t)q * LEVELS + l) * 2];
        const float ry = rp[((size_t)q * LEVELS + l) * 2 + 1];
        const int W = c_LW[l], H = c_LH[l], st = c_LS[l];

        const float locx = rx + offx / (float)W;
        const float locy = ry + offy / (float)H;
        const float x = locx * (float)W - 0.5f;
        const float y = locy * (float)H - 0.5f;
        const float x0f = floorf(x), y0f = floorf(y);
        const float lx = x - x0f, ly = y - y0f;
        const int x0 = (int)x0f, y0 = (int)y0f;

#pragma unroll
        for (int cc = 0; cc < 4; cc++) {
            const int dx = cc & 1, dy = cc >> 1;
            const int xi = x0 + dx, yi = y0 + dy;
            const float wx = dx ? lx : (1.f - lx);
            const float wy = dy ? ly : (1.f - ly);
            const bool valid = (xi >= 0) && (xi < W) && (yi >= 0) && (yi < H);
            const int xc = min(max(xi, 0), W - 1);
            const int yc = min(max(yi, 0), H - 1);
            s_pos[qi][s][cc] = st + yc * W + xc;
            s_wt[qi][s][cc] = valid ? (wx * wy * aw) : 0.f;
        }
    }
    __syncthreads();

    const int h = tq >> 4;
    const int d2 = tq & 15;
    const int ch = h * 32 + d2 * 2;
    const __half* vb = g_vh + (size_t)b * NV * EMBED + ch;
    float2 acc = make_float2(0.f, 0.f);
#pragma unroll
    for (int i = 0; i < 16; i++) {
        const int s = h * 16 + i;
#pragma unroll
        for (int cc = 0; cc < 4; cc++) {
            const float w = s_wt[qi][s][cc];
            const __half2 hv = *reinterpret_cast<const __half2*>(vb + (size_t)s_pos[qi][s][cc] * EMBED);
            const float2 f = __half22float2(hv);
            acc.x = fmaf(w, f.x, acc.x);
            acc.y = fmaf(w, f.y, acc.y);
        }
    }
    *reinterpret_cast<float2*>(&g_attn[(size_t)q * EMBED + ch]) = acc;
}

// ---------------- launch ----------------
extern "C" void kernel_launch(void* const* d_in, const int* in_sizes, int n_in,
                              void* d_out, int out_size)
{
    const float* query  = (const float*)d_in[0];
    const float* value  = (const float*)d_in[1];
    const float* rp     = (const float*)d_in[2];
    const float* W_off  = (const float*)d_in[4];
    const float* b_off  = (const float*)d_in[5];
    const float* W_attn = (const float*)d_in[6];
    const float* b_attn = (const float*)d_in[7];
    const float* W_v    = (const float*)d_in[8];
    const float* b_v    = (const float*)d_in[9];
    const float* W_out  = (const float*)d_in[10];
    const float* b_out  = (const float*)d_in[11];
    float* out = (float*)d_out;

    float *pqa, *pattn, *pbias_qa;
    __half* pvh;
    cudaGetSymbolAddress((void**)&pvh,      g_vh);
    cudaGetSymbolAddress((void**)&pqa,      g_qa);
    cudaGetSymbolAddress((void**)&pattn,    g_attn);
    cudaGetSymbolAddress((void**)&pbias_qa, g_bias_qa);

    __half *bvh, *bvl, *bqh, *bql, *buh, *bul;
    cudaGetSymbolAddress((void**)&bvh, g_Bvh); cudaGetSymbolAddress((void**)&bvl, g_Bvl);
    cudaGetSymbolAddress((void**)&bqh, g_Bqh); cudaGetSymbolAddress((void**)&bql, g_Bql);
    cudaGetSymbolAddress((void**)&buh, g_Buh); cudaGetSymbolAddress((void**)&bul, g_Bul);

    const int DS64  = 2 * ((128 + 2 * 64) * ROWB);    // 40960 (TERMS=2, BN=64)
    const int DS256 = 2 * ((128 + 1 * 256) * ROWB);   // 61440 (TERMS=1, BN=256)
    cudaFuncSetAttribute((const void*)mma_gemm_kernel<2, 64, 2>,
                         cudaFuncAttributeMaxDynamicSharedMemorySize, DS64);
    cudaFuncSetAttribute((const void*)mma_gemm_kernel<1, 256, 1>,
                         cudaFuncAttributeMaxDynamicSharedMemorySize, DS256);

    static cudaStream_t s2 = nullptr;
    static cudaEvent_t evFork = nullptr, evJoin = nullptr;
    if (!s2) {
        cudaStreamCreateWithFlags(&s2, cudaStreamNonBlocking);
        cudaEventCreateWithFlags(&evFork, cudaEventDisableTiming);
        cudaEventCreateWithFlags(&evJoin, cudaEventDisableTiming);
    }

    // fork immediately: value-path on main, query-path on s2
    cudaEventRecord(evFork, 0);
    cudaStreamWaitEvent(s2, evFork, 0);

    // main stream: conv_v -> value GEMM (BN=256, single-term)
    conv_v_kernel<<<256, 256>>>(W_v);
    const int Mv = BS * NV;
    {
        dim3 grid(1, (Mv + 127) / 128);
        mma_gemm_kernel<1, 256, 1><<<grid, 256, DS256>>>(value, bvh, bvl, b_v, nullptr,
                                                         nullptr, pvh, Mv, 256);
    }

    // s2: conv_rest -> fused offsets+logits GEMM (ordered on the SAME stream)
    conv_rest_kernel<<<642, 256, 0, s2>>>(W_off, W_attn, W_out, b_off, b_attn);
    {
        dim3 grid(6, (NBQ + 127) / 128);
        mma_gemm_kernel<2, 64, 2><<<grid, 256, DS64, s2>>>(query, bqh, bql, pbias_qa, nullptr,
                                                           pqa, nullptr, NBQ, 384);
    }

    // join
    cudaEventRecord(evJoin, s2);
    cudaStreamWaitEvent(0, evJoin, 0);

    msda_sample_kernel<<<NBQ / 2, 256>>>(rp);

    {   // output projection + residual: 2-term, BN=64
        dim3 grid(4, (NBQ + 127) / 128);
        mma_gemm_kernel<2, 64, 2><<<grid, 256, DS64>>>(pattn, buh, bul, b_out, query,
                                                       out, nullptr, NBQ, 256);
    }
}